// round 9
// baseline (speedup 1.0000x reference)
#include <cuda_runtime.h>
#include <cuda_bf16.h>
#include <math.h>
#include <stdint.h>

// Problem constants (fixed shapes from setup_inputs)
#define BB  8
#define CC  192
#define HH  56
#define WW  56
#define NN  3136            // H*W
#define CC2 384             // 2*C
#define CG  96              // C2/4
#define KNB 9               // K_NEIGHBORS
#define BNEPS 1e-5f
#define KTOT 576            // 3*CC  (hi|hi|lo concat)
#define NSLAB 18            // KTOT/32
#define SA 40               // smem row stride in bf16 (32 + 8 pad)

// ---------------- scratch (static device globals; no runtime alloc) --------
__device__ float d_peT [CC * NN];                          //  2.4 MB (K-major)
__device__ float d_rel [(size_t)NN * NN + 64];             // 39.3 MB
__device__ float d_h   [(size_t)BB * NN * CC];             // 19.3 MB
__device__ __nv_bfloat16 d_xa[(size_t)BB * NN * KTOT];     // 28.9 MB  [hi|hi|lo]
__device__ __nv_bfloat16 d_xb[(size_t)BB * NN * KTOT];     // 28.9 MB  [hi|lo|hi]
__device__ float d_sq  [BB * NN];
__device__ float d_dist[(size_t)BB * NN * NN];             // 314.7 MB
__device__ float d_gbuf[(size_t)BB * NN * CC2];            // 38.6 MB
__device__ float d_ybuf[(size_t)BB * NN * CC2];            // 38.6 MB
__device__ float d_obuf[(size_t)BB * NN * CC];             // 19.3 MB

__device__ __forceinline__ uint32_t smem_u32(const void* p) {
    uint32_t a;
    asm("{ .reg .u64 t; cvta.to.shared.u64 t, %1; cvt.u32.u64 %0, t; }"
        : "=r"(a) : "l"(p));
    return a;
}

// ---------------- positional embedding (K-major write, coalesced) -----------
__global__ void pe_kernel() {
    int i = blockIdx.x * blockDim.x + threadIdx.x;
    if (i >= NN * CC) return;
    int k = i / NN, n = i % NN;
    int yy = n / WW, xx = n % WW;
    float pos = (k < 96) ? (float)yy : (float)xx;
    int kk = k % 96;
    int oi = (kk < 48) ? kk : kk - 48;
    float omega = expf(-logf(10000.0f) * (float)oi / 48.0f);
    float ang = pos * omega;
    d_peT[i] = (kk < 48) ? sinf(ang) : cosf(ang);
}

// ---------------- 128x128x16 double-buffered SGEMM (modes 0,1,3,4) ----------
template <int MODE>
__global__ void __launch_bounds__(256, 2)
gemm_kernel(const float* __restrict__ Ain, const float* __restrict__ Bin,
            const float* __restrict__ q0, const float* __restrict__ q1,
            const float* __restrict__ q2, const float* __restrict__ q3,
            const float* __restrict__ q4)
{
    if (MODE == 1 && blockIdx.y > blockIdx.x) return;

    constexpr bool AKM = (MODE <= 1);
    constexpr bool BKM = (MODE == 1);

    int M, Nc, K, lda, ldb;
    const float* A;
    const float* B;
    const int bz = blockIdx.z;

    if (MODE == 0) {
        A = Ain + (size_t)bz * CC * NN;  B = Bin;
        M = NN; Nc = CC; K = CC; lda = NN; ldb = CC;
    } else if (MODE == 1) {
        A = d_peT; B = d_peT;
        M = NN; Nc = NN; K = CC; lda = NN; ldb = NN;
    } else if (MODE == 3) {
        int b = bz >> 2, g = bz & 3;
        A = d_gbuf + (size_t)b * NN * CC2 + g * CG;
        B = Bin + (size_t)g * CG * CG;
        M = NN; Nc = CG; K = CG; lda = CC2; ldb = CG;
    } else {
        A = d_ybuf; B = Bin;
        M = BB * NN; Nc = CC; K = CC2; lda = CC2; ldb = CC2;
    }

    __shared__ float As[2][16][128];
    __shared__ float Bs[2][16][128];

    const int tid = threadIdx.x;
    const int tx = tid & 15;
    const int ty = tid >> 4;
    const int m0 = blockIdx.y * 128;
    const int n0 = blockIdx.x * 128;

    const float* aptr0;
    const float* aptr1;
    int a_km_k = 0, a_km_m = 0;
    int a_rm_r = 0, a_rm_kq = 0;
    if (AKM) {
        a_km_k = tid >> 5;
        a_km_m = (tid & 31) * 4;
        int mc = min(m0 + a_km_m, M - 4);
        aptr0 = A + (size_t)a_km_k * lda + mc;
        aptr1 = A + (size_t)(a_km_k + 8) * lda + mc;
    } else {
        a_rm_r  = tid >> 1;
        a_rm_kq = (tid & 1) * 8;
        int rc = min(m0 + a_rm_r, M - 1);
        aptr0 = A + (size_t)rc * lda + a_rm_kq;
        aptr1 = aptr0 + 4;
    }
    const float* bptr0;
    const float* bptr1;
    int b_km_k = 0, b_km_n = 0;
    int b_rm_r = 0, b_rm_kq = 0;
    if (BKM) {
        b_km_k = tid >> 5;
        b_km_n = (tid & 31) * 4;
        int nc = min(n0 + b_km_n, Nc - 4);
        bptr0 = B + (size_t)b_km_k * ldb + nc;
        bptr1 = B + (size_t)(b_km_k + 8) * ldb + nc;
    } else {
        b_rm_r  = tid >> 1;
        b_rm_kq = (tid & 1) * 8;
        int rc = min(n0 + b_rm_r, Nc - 1);
        bptr0 = B + (size_t)rc * ldb + b_rm_kq;
        bptr1 = bptr0 + 4;
    }

    float4 ra0, ra1, rb0, rb1;
    ra0 = *reinterpret_cast<const float4*>(aptr0);
    ra1 = *reinterpret_cast<const float4*>(aptr1);
    rb0 = *reinterpret_cast<const float4*>(bptr0);
    rb1 = *reinterpret_cast<const float4*>(bptr1);
    if (AKM) {
        *reinterpret_cast<float4*>(&As[0][a_km_k][a_km_m])     = ra0;
        *reinterpret_cast<float4*>(&As[0][a_km_k + 8][a_km_m]) = ra1;
    } else {
        As[0][a_rm_kq + 0][a_rm_r] = ra0.x; As[0][a_rm_kq + 1][a_rm_r] = ra0.y;
        As[0][a_rm_kq + 2][a_rm_r] = ra0.z; As[0][a_rm_kq + 3][a_rm_r] = ra0.w;
        As[0][a_rm_kq + 4][a_rm_r] = ra1.x; As[0][a_rm_kq + 5][a_rm_r] = ra1.y;
        As[0][a_rm_kq + 6][a_rm_r] = ra1.z; As[0][a_rm_kq + 7][a_rm_r] = ra1.w;
    }
    if (BKM) {
        *reinterpret_cast<float4*>(&Bs[0][b_km_k][b_km_n])     = rb0;
        *reinterpret_cast<float4*>(&Bs[0][b_km_k + 8][b_km_n]) = rb1;
    } else {
        Bs[0][b_rm_kq + 0][b_rm_r] = rb0.x; Bs[0][b_rm_kq + 1][b_rm_r] = rb0.y;
        Bs[0][b_rm_kq + 2][b_rm_r] = rb0.z; Bs[0][b_rm_kq + 3][b_rm_r] = rb0.w;
        Bs[0][b_rm_kq + 4][b_rm_r] = rb1.x; Bs[0][b_rm_kq + 5][b_rm_r] = rb1.y;
        Bs[0][b_rm_kq + 6][b_rm_r] = rb1.z; Bs[0][b_rm_kq + 7][b_rm_r] = rb1.w;
    }
    __syncthreads();

    float acc[8][8];
#pragma unroll
    for (int i = 0; i < 8; i++)
#pragma unroll
        for (int j = 0; j < 8; j++) acc[i][j] = 0.0f;

    const int T = K >> 4;
    for (int t = 0; t < T; t++) {
        const int cur = t & 1;
        if (t + 1 < T) {
            if (AKM) { aptr0 += (size_t)16 * lda; aptr1 += (size_t)16 * lda; }
            else     { aptr0 += 16;               aptr1 += 16; }
            if (BKM) { bptr0 += (size_t)16 * ldb; bptr1 += (size_t)16 * ldb; }
            else     { bptr0 += 16;               bptr1 += 16; }
            ra0 = *reinterpret_cast<const float4*>(aptr0);
            ra1 = *reinterpret_cast<const float4*>(aptr1);
            rb0 = *reinterpret_cast<const float4*>(bptr0);
            rb1 = *reinterpret_cast<const float4*>(bptr1);
        }
#pragma unroll
        for (int kk = 0; kk < 16; kk++) {
            float af[8], bf[8];
            *reinterpret_cast<float4*>(&af[0]) = *reinterpret_cast<const float4*>(&As[cur][kk][ty * 4]);
            *reinterpret_cast<float4*>(&af[4]) = *reinterpret_cast<const float4*>(&As[cur][kk][64 + ty * 4]);
            *reinterpret_cast<float4*>(&bf[0]) = *reinterpret_cast<const float4*>(&Bs[cur][kk][tx * 4]);
            *reinterpret_cast<float4*>(&bf[4]) = *reinterpret_cast<const float4*>(&Bs[cur][kk][64 + tx * 4]);
#pragma unroll
            for (int i = 0; i < 8; i++)
#pragma unroll
                for (int j = 0; j < 8; j++) acc[i][j] += af[i] * bf[j];
        }
        if (t + 1 < T) {
            const int nxt = cur ^ 1;
            if (AKM) {
                *reinterpret_cast<float4*>(&As[nxt][a_km_k][a_km_m])     = ra0;
                *reinterpret_cast<float4*>(&As[nxt][a_km_k + 8][a_km_m]) = ra1;
            } else {
                As[nxt][a_rm_kq + 0][a_rm_r] = ra0.x; As[nxt][a_rm_kq + 1][a_rm_r] = ra0.y;
                As[nxt][a_rm_kq + 2][a_rm_r] = ra0.z; As[nxt][a_rm_kq + 3][a_rm_r] = ra0.w;
                As[nxt][a_rm_kq + 4][a_rm_r] = ra1.x; As[nxt][a_rm_kq + 5][a_rm_r] = ra1.y;
                As[nxt][a_rm_kq + 6][a_rm_r] = ra1.z; As[nxt][a_rm_kq + 7][a_rm_r] = ra1.w;
            }
            if (BKM) {
                *reinterpret_cast<float4*>(&Bs[nxt][b_km_k][b_km_n])     = rb0;
                *reinterpret_cast<float4*>(&Bs[nxt][b_km_k + 8][b_km_n]) = rb1;
            } else {
                Bs[nxt][b_rm_kq + 0][b_rm_r] = rb0.x; Bs[nxt][b_rm_kq + 1][b_rm_r] = rb0.y;
                Bs[nxt][b_rm_kq + 2][b_rm_r] = rb0.z; Bs[nxt][b_rm_kq + 3][b_rm_r] = rb0.w;
                Bs[nxt][b_rm_kq + 4][b_rm_r] = rb1.x; Bs[nxt][b_rm_kq + 5][b_rm_r] = rb1.y;
                Bs[nxt][b_rm_kq + 6][b_rm_r] = rb1.z; Bs[nxt][b_rm_kq + 7][b_rm_r] = rb1.w;
            }
        }
        __syncthreads();
    }

    int rows[8], cols[8];
#pragma unroll
    for (int i = 0; i < 4; i++) {
        rows[i]     = m0 + ty * 4 + i;
        rows[i + 4] = m0 + 64 + ty * 4 + i;
        cols[i]     = n0 + tx * 4 + i;
        cols[i + 4] = n0 + 64 + tx * 4 + i;
    }

    if (MODE == 1) {
        const float sc = -2.0f / (float)CC;
#pragma unroll
        for (int i = 0; i < 8; i++) {
            if (rows[i] >= M) continue;
            float* rr = d_rel + (size_t)rows[i] * NN;
#pragma unroll
            for (int j = 0; j < 8; j++)
                if (cols[j] < Nc) rr[cols[j]] = sc * acc[i][j];
        }
        if (blockIdx.y != blockIdx.x) {
            const bool full0 = (rows[3] < M);
            const bool full1 = (rows[7] < M);
#pragma unroll
            for (int j = 0; j < 8; j++) {
                int m = cols[j];
                if (m >= Nc) continue;
                float* base = &d_rel[(size_t)m * NN];
                if (full0) {
                    float4 v;
                    v.x = sc * acc[0][j]; v.y = sc * acc[1][j];
                    v.z = sc * acc[2][j]; v.w = sc * acc[3][j];
                    *reinterpret_cast<float4*>(&base[rows[0]]) = v;
                } else {
#pragma unroll
                    for (int i = 0; i < 4; i++)
                        if (rows[i] < M) base[rows[i]] = sc * acc[i][j];
                }
                if (full1) {
                    float4 v;
                    v.x = sc * acc[4][j]; v.y = sc * acc[5][j];
                    v.z = sc * acc[6][j]; v.w = sc * acc[7][j];
                    *reinterpret_cast<float4*>(&base[rows[4]]) = v;
                } else {
#pragma unroll
                    for (int i = 4; i < 8; i++)
                        if (rows[i] < M) base[rows[i]] = sc * acc[i][j];
                }
            }
        }
    } else if (MODE == 0) {
        float sc[8], bi[8];
#pragma unroll
        for (int j = 0; j < 8; j++) {
            if (cols[j] < Nc) {
                float s = q1[cols[j]] * rsqrtf(q4[cols[j]] + BNEPS);
                sc[j] = s;
                bi[j] = (q0[cols[j]] - q3[cols[j]]) * s + q2[cols[j]];
            } else { sc[j] = 0.f; bi[j] = 0.f; }
        }
        float* hb = d_h + (size_t)bz * NN * CC;
#pragma unroll
        for (int i = 0; i < 8; i++) {
            if (rows[i] >= M) continue;
#pragma unroll
            for (int j = 0; j < 8; j++)
                if (cols[j] < Nc)
                    hb[(size_t)rows[i] * CC + cols[j]] = acc[i][j] * sc[j] + bi[j];
        }
    } else if (MODE == 3) {
        int b = bz >> 2, g = bz & 3;
        float sc[8], bi[8];
        int ch[8];
#pragma unroll
        for (int j = 0; j < 8; j++) {
            ch[j] = g * CG + cols[j];
            if (cols[j] < Nc) {
                float s = q1[ch[j]] * rsqrtf(q4[ch[j]] + BNEPS);
                sc[j] = s;
                bi[j] = (q0[ch[j]] - q3[ch[j]]) * s + q2[ch[j]];
            } else { sc[j] = 0.f; bi[j] = 0.f; }
        }
        float* yb = d_ybuf + (size_t)b * NN * CC2;
#pragma unroll
        for (int i = 0; i < 8; i++) {
            if (rows[i] >= M) continue;
#pragma unroll
            for (int j = 0; j < 8; j++)
                if (cols[j] < Nc) {
                    float t2 = acc[i][j] * sc[j] + bi[j];
                    yb[(size_t)rows[i] * CC2 + ch[j]] = t2 * normcdff(t2);
                }
        }
    } else { // MODE 4
        float sc[8], bi[8];
#pragma unroll
        for (int j = 0; j < 8; j++) {
            if (cols[j] < Nc) {
                float s = q1[cols[j]] * rsqrtf(q4[cols[j]] + BNEPS);
                sc[j] = s;
                bi[j] = (q0[cols[j]] - q3[cols[j]]) * s + q2[cols[j]];
            } else { sc[j] = 0.f; bi[j] = 0.f; }
        }
#pragma unroll
        for (int i = 0; i < 8; i++) {
            if (rows[i] >= M) continue;
#pragma unroll
            for (int j = 0; j < 8; j++)
                if (cols[j] < Nc)
                    d_obuf[(size_t)rows[i] * CC + cols[j]] = acc[i][j] * sc[j] + bi[j];
        }
    }
}

// ---------------- L2 normalize + sq + bf16 hi/lo concat buffers --------------
__global__ void norm_kernel() {
    int row = blockIdx.x;
    const float* hr = d_h + (size_t)row * CC;
    int t = threadIdx.x;                    // 64 threads
    float a0 = hr[t], a1 = hr[t + 64], a2 = hr[t + 128];
    float ss = a0 * a0 + a1 * a1 + a2 * a2;
#pragma unroll
    for (int o = 16; o > 0; o >>= 1) ss += __shfl_down_sync(0xffffffffu, ss, o);
    __shared__ float w1[2], w2[2];
    if ((t & 31) == 0) w1[t >> 5] = ss;
    __syncthreads();
    float norm = sqrtf(w1[0] + w1[1]);
    float inv = 1.0f / fmaxf(norm, 1e-12f);
    float xv[3] = { a0 * inv, a1 * inv, a2 * inv };
    float s2 = xv[0] * xv[0] + xv[1] * xv[1] + xv[2] * xv[2];
#pragma unroll
    for (int o = 16; o > 0; o >>= 1) s2 += __shfl_down_sync(0xffffffffu, s2, o);
    if ((t & 31) == 0) w2[t >> 5] = s2;

    __nv_bfloat16* xa = d_xa + (size_t)row * KTOT;
    __nv_bfloat16* xb = d_xb + (size_t)row * KTOT;
#pragma unroll
    for (int e = 0; e < 3; e++) {
        int c = t + e * 64;
        float x = xv[e];
        __nv_bfloat16 h = __float2bfloat16(x);
        __nv_bfloat16 l = __float2bfloat16(x - __bfloat162float(h));
        xa[c]       = h;  xa[192 + c] = h;  xa[384 + c] = l;
        xb[c]       = h;  xb[192 + c] = l;  xb[384 + c] = h;
    }
    __syncthreads();
    if (t == 0) d_sq[row] = w2[0] + w2[1];
}

// ---------------- dist via mma.sync bf16 (K=576 concat split) ----------------
// CTA 128x128, 8 warps as 4(m)x2(n); warp tile 32x64; K-slab 32, double-buffered.
#define ABUF_B (128 * SA * 2)                 // 10240 bytes per buffer
#define DSM_TOTAL (128 * 132 * 4)             // 67584 bytes (>= 4*ABUF_B)
__global__ void __launch_bounds__(256)
dist_mma_kernel() {
    if (blockIdx.y > blockIdx.x) return;
    extern __shared__ char smem[];
    const int tid = threadIdx.x, w = tid >> 5, lane = tid & 31;
    const int b = blockIdx.z;
    const int m0 = blockIdx.y * 128, n0 = blockIdx.x * 128;

    __nv_bfloat16* sAb[2] = { (__nv_bfloat16*)(smem),
                              (__nv_bfloat16*)(smem + ABUF_B) };
    __nv_bfloat16* sBb[2] = { (__nv_bfloat16*)(smem + 2 * ABUF_B),
                              (__nv_bfloat16*)(smem + 3 * ABUF_B) };

    // per-thread global load coords
    const int lrow = tid >> 1;
    const int lofs = (tid & 1) * 16;
    const __nv_bfloat16* pA = d_xa + (size_t)b * NN * KTOT
                            + (size_t)min(m0 + lrow, NN - 1) * KTOT + lofs;
    const __nv_bfloat16* pB = d_xb + (size_t)b * NN * KTOT
                            + (size_t)min(n0 + lrow, NN - 1) * KTOT + lofs;

    // prologue: slab 0
    uint4 va0 = *reinterpret_cast<const uint4*>(pA);
    uint4 va1 = *reinterpret_cast<const uint4*>(pA + 8);
    uint4 vb0 = *reinterpret_cast<const uint4*>(pB);
    uint4 vb1 = *reinterpret_cast<const uint4*>(pB + 8);
    *reinterpret_cast<uint4*>(sAb[0] + lrow * SA + lofs)     = va0;
    *reinterpret_cast<uint4*>(sAb[0] + lrow * SA + lofs + 8) = va1;
    *reinterpret_cast<uint4*>(sBb[0] + lrow * SA + lofs)     = vb0;
    *reinterpret_cast<uint4*>(sBb[0] + lrow * SA + lofs + 8) = vb1;
    __syncthreads();

    float acc[2][8][4];
#pragma unroll
    for (int i = 0; i < 2; i++)
#pragma unroll
        for (int j = 0; j < 8; j++)
#pragma unroll
            for (int k = 0; k < 4; k++) acc[i][j][k] = 0.0f;

    const int wm = w & 3;        // rows wm*32
    const int wn = w >> 2;       // cols wn*64
    const int aRow = lane & 15;
    const int aColH = (lane >> 4) * 8;
    const int bN = ((lane >> 4) << 3) + (lane & 7);
    const int bColH = ((lane >> 3) & 1) * 8;

    for (int s = 0; s < NSLAB; s++) {
        const int cur = s & 1;
        if (s + 1 < NSLAB) {
            pA += 32; pB += 32;
            va0 = *reinterpret_cast<const uint4*>(pA);
            va1 = *reinterpret_cast<const uint4*>(pA + 8);
            vb0 = *reinterpret_cast<const uint4*>(pB);
            vb1 = *reinterpret_cast<const uint4*>(pB + 8);
        }
#pragma unroll
        for (int kk = 0; kk < 2; kk++) {
            const int k0 = kk * 16;
            uint32_t af[2][4];
#pragma unroll
            for (int mi = 0; mi < 2; mi++) {
                uint32_t addr = smem_u32(sAb[cur]
                    + (wm * 32 + mi * 16 + aRow) * SA + k0 + aColH);
                asm volatile(
                    "ldmatrix.sync.aligned.m8n8.x4.shared.b16 {%0,%1,%2,%3}, [%4];"
                    : "=r"(af[mi][0]), "=r"(af[mi][1]), "=r"(af[mi][2]), "=r"(af[mi][3])
                    : "r"(addr));
            }
            uint32_t bfv[4][4];
#pragma unroll
            for (int nb = 0; nb < 4; nb++) {
                uint32_t addr = smem_u32(sBb[cur]
                    + (wn * 64 + nb * 16 + bN) * SA + k0 + bColH);
                asm volatile(
                    "ldmatrix.sync.aligned.m8n8.x4.shared.b16 {%0,%1,%2,%3}, [%4];"
                    : "=r"(bfv[nb][0]), "=r"(bfv[nb][1]), "=r"(bfv[nb][2]), "=r"(bfv[nb][3])
                    : "r"(addr));
            }
#pragma unroll
            for (int mi = 0; mi < 2; mi++)
#pragma unroll
                for (int ni = 0; ni < 8; ni++) {
                    uint32_t b0 = bfv[ni >> 1][(ni & 1) * 2 + 0];
                    uint32_t b1 = bfv[ni >> 1][(ni & 1) * 2 + 1];
                    asm volatile(
                        "mma.sync.aligned.m16n8k16.row.col.f32.bf16.bf16.f32 "
                        "{%0,%1,%2,%3}, {%4,%5,%6,%7}, {%8,%9}, {%0,%1,%2,%3};"
                        : "+f"(acc[mi][ni][0]), "+f"(acc[mi][ni][1]),
                          "+f"(acc[mi][ni][2]), "+f"(acc[mi][ni][3])
                        : "r"(af[mi][0]), "r"(af[mi][1]), "r"(af[mi][2]), "r"(af[mi][3]),
                          "r"(b0), "r"(b1));
                }
        }
        if (s + 1 < NSLAB) {
            const int nxt = cur ^ 1;
            __syncthreads();   // all LDSM of cur done before overwriting nxt? (nxt != cur; only needed before reuse of nxt)
            *reinterpret_cast<uint4*>(sAb[nxt] + lrow * SA + lofs)     = va0;
            *reinterpret_cast<uint4*>(sAb[nxt] + lrow * SA + lofs + 8) = va1;
            *reinterpret_cast<uint4*>(sBb[nxt] + lrow * SA + lofs)     = vb0;
            *reinterpret_cast<uint4*>(sBb[nxt] + lrow * SA + lofs + 8) = vb1;
            __syncthreads();
        }
    }
    __syncthreads();

    // ---- stage C to smem [128][132]
    float* Ds = reinterpret_cast<float*>(smem);
#pragma unroll
    for (int mi = 0; mi < 2; mi++) {
        int r0 = wm * 32 + mi * 16 + (lane >> 2);
        int c0 = wn * 64 + (lane & 3) * 2;
#pragma unroll
        for (int ni = 0; ni < 8; ni++) {
            int cc = c0 + ni * 8;
            Ds[r0 * 132 + cc]           = acc[mi][ni][0];
            Ds[r0 * 132 + cc + 1]       = acc[mi][ni][1];
            Ds[(r0 + 8) * 132 + cc]     = acc[mi][ni][2];
            Ds[(r0 + 8) * 132 + cc + 1] = acc[mi][ni][3];
        }
    }
    __syncthreads();

    float* db = d_dist + (size_t)b * NN * NN;
    const float* sqb = d_sq + b * NN;

    // phase 1: mirror tile (coalesced along rows; rel read via symmetry)
    if (blockIdx.x != blockIdx.y) {
        for (int cl = w; cl < 128; cl += 8) {
            int m = n0 + cl;
            if (m >= NN) break;
            const float* relm = d_rel + (size_t)m * NN;
            float* dbm = db + (size_t)m * NN;
            int r4 = lane * 4;
            int rg = m0 + r4;
            if (rg + 3 < NN) {
                float4 dv;
                dv.x = Ds[(r4 + 0) * 132 + cl];
                dv.y = Ds[(r4 + 1) * 132 + cl];
                dv.z = Ds[(r4 + 2) * 132 + cl];
                dv.w = Ds[(r4 + 3) * 132 + cl];
                float4 rv = *reinterpret_cast<const float4*>(relm + rg);
                float4 sq4 = *reinterpret_cast<const float4*>(sqb + rg);
                float4 o;
                o.x = sq4.x - 2.0f * dv.x + rv.x;
                o.y = sq4.y - 2.0f * dv.y + rv.y;
                o.z = sq4.z - 2.0f * dv.z + rv.z;
                o.w = sq4.w - 2.0f * dv.w + rv.w;
                *reinterpret_cast<float4*>(dbm + rg) = o;
            } else {
#pragma unroll
                for (int i = 0; i < 4; i++)
                    if (rg + i < NN)
                        dbm[rg + i] = sqb[rg + i]
                            - 2.0f * Ds[(r4 + i) * 132 + cl] + relm[rg + i];
            }
        }
    }

    // phase 2: normal tile (row-coalesced)
#pragma unroll 1
    for (int it = 0; it < 16; it++) {
        int f = tid + it * 256;
        int rl = f >> 5, c4 = f & 31;
        int rg = m0 + rl;
        if (rg >= NN) continue;
        int gc = n0 + c4 * 4;
        float4 dv = *reinterpret_cast<const float4*>(&Ds[rl * 132 + c4 * 4]);
        const float* relrow = d_rel + (size_t)rg * NN;
        float* dd = db + (size_t)rg * NN;
        if (gc + 3 < NN) {
            float4 rv = *reinterpret_cast<const float4*>(&relrow[gc]);
            float4 sq4 = *reinterpret_cast<const float4*>(sqb + gc);
            float4 o;
            o.x = sq4.x - 2.0f * dv.x + rv.x;
            o.y = sq4.y - 2.0f * dv.y + rv.y;
            o.z = sq4.z - 2.0f * dv.z + rv.z;
            o.w = sq4.w - 2.0f * dv.w + rv.w;
            *reinterpret_cast<float4*>(&dd[gc]) = o;
        } else {
            float dvv[4] = { dv.x, dv.y, dv.z, dv.w };
#pragma unroll
            for (int i = 0; i < 4; i++)
                if (gc + i < NN)
                    dd[gc + i] = sqb[gc + i] - 2.0f * dvv[i] + relrow[gc + i];
        }
    }
}

// ---------------- fused top-9 + gather/max-edge ------------------------------
__global__ void __launch_bounds__(256) topk_gather_kernel() {
    const int row = blockIdx.x;
    const int b = row / NN, n = row % NN;
    const float4* dr4 = reinterpret_cast<const float4*>(
        d_dist + (size_t)b * NN * NN + (size_t)n * NN);

    float tv[KNB];
    int   ti[KNB];
#pragma unroll
    for (int q = 0; q < KNB; q++) { tv[q] = INFINITY; ti[q] = 0x7fffffff; }

    for (int i4 = threadIdx.x; i4 < NN / 4; i4 += 256) {
        float4 v4 = dr4[i4];
        const int mb = i4 * 4;
        float vv[4] = { v4.x, v4.y, v4.z, v4.w };
#pragma unroll
        for (int c = 0; c < 4; c++) {
            float v = vv[c];
            if (v < tv[KNB - 1]) {
                tv[KNB - 1] = v; ti[KNB - 1] = mb + c;
#pragma unroll
                for (int q = KNB - 1; q > 0; q--) {
                    if (tv[q] < tv[q - 1]) {
                        float fv = tv[q]; tv[q] = tv[q - 1]; tv[q - 1] = fv;
                        int   fi = ti[q]; ti[q] = ti[q - 1]; ti[q - 1] = fi;
                    }
                }
            }
        }
    }

    __shared__ float sv[256 * KNB];
    __shared__ int   si[256 * KNB];
#pragma unroll
    for (int q = 0; q < KNB; q++) { sv[threadIdx.x * KNB + q] = tv[q]; si[threadIdx.x * KNB + q] = ti[q]; }

    for (int stride = 128; stride >= 1; stride >>= 1) {
        __syncthreads();
        if (threadIdx.x < (unsigned)stride) {
            float* Av = &sv[threadIdx.x * KNB];
            int*   Ai = &si[threadIdx.x * KNB];
            float* Bv = &sv[(threadIdx.x + stride) * KNB];
            int*   Bi = &si[(threadIdx.x + stride) * KNB];
            float ov[KNB]; int oi[KNB];
            int ia = 0, ib = 0;
#pragma unroll
            for (int q = 0; q < KNB; q++) {
                float va = (ia < KNB) ? Av[ia] : INFINITY;
                float vb = (ib < KNB) ? Bv[ib] : INFINITY;
                int xa = (ia < KNB) ? Ai[ia] : 0x7fffffff;
                int xb = (ib < KNB) ? Bi[ib] : 0x7fffffff;
                bool takeA = (va < vb) || (va == vb && xa < xb);
                ov[q] = takeA ? va : vb;
                oi[q] = takeA ? xa : xb;
                if (takeA) ia++; else ib++;
            }
#pragma unroll
            for (int q = 0; q < KNB; q++) { Av[q] = ov[q]; Ai[q] = oi[q]; }
        }
    }
    __syncthreads();

    if (threadIdx.x < CC) {
        const int c = threadIdx.x;
        const float* hb = d_h + (size_t)b * NN * CC;
        float hn = d_h[(size_t)row * CC + c];
        float mx = -INFINITY;
#pragma unroll
        for (int j = 0; j < KNB; j++)
            mx = fmaxf(mx, hb[(size_t)si[j] * CC + c] - hn);
        d_gbuf[(size_t)row * CC2 + c]      = hn;
        d_gbuf[(size_t)row * CC2 + CC + c] = mx;
    }
}

// ---------------- transpose (B,N,C)->(B,C,N) + residual ---------------------
__global__ void out_kernel(const float* __restrict__ x, float* __restrict__ out) {
    __shared__ float tile[32][33];
    const int b = blockIdx.z;
    const int n0 = blockIdx.x * 32, c0 = blockIdx.y * 32;
    const int tx = threadIdx.x, ty = threadIdx.y;
#pragma unroll
    for (int i = 0; i < 32; i += 8)
        tile[ty + i][tx] = d_obuf[((size_t)b * NN + n0 + ty + i) * CC + c0 + tx];
    __syncthreads();
#pragma unroll
    for (int i = 0; i < 32; i += 8) {
        int c = c0 + ty + i, n = n0 + tx;
        size_t o = ((size_t)b * CC + c) * NN + n;
        out[o] = tile[tx][ty + i] + x[o];
    }
}

// ---------------- launch ----------------------------------------------------
extern "C" void kernel_launch(void* const* d_in, const int* in_sizes, int n_in,
                              void* d_out, int out_size)
{
    (void)in_sizes; (void)n_in; (void)out_size;
    const float* x     = (const float*)d_in[0];
    const float* fc1_w = (const float*)d_in[1];
    const float* fc1_b = (const float*)d_in[2];
    const float* bn1_g = (const float*)d_in[3];
    const float* bn1_b = (const float*)d_in[4];
    const float* bn1_m = (const float*)d_in[5];
    const float* bn1_v = (const float*)d_in[6];
    const float* gc_w  = (const float*)d_in[7];
    const float* gc_b  = (const float*)d_in[8];
    const float* bng_g = (const float*)d_in[9];
    const float* bng_b = (const float*)d_in[10];
    const float* bng_m = (const float*)d_in[11];
    const float* bng_v = (const float*)d_in[12];
    const float* fc2_w = (const float*)d_in[13];
    const float* fc2_b = (const float*)d_in[14];
    const float* bn2_g = (const float*)d_in[15];
    const float* bn2_b = (const float*)d_in[16];
    const float* bn2_m = (const float*)d_in[17];
    const float* bn2_v = (const float*)d_in[18];
    float* out = (float*)d_out;

    cudaFuncSetAttribute(dist_mma_kernel,
                         cudaFuncAttributeMaxDynamicSharedMemorySize, DSM_TOTAL);

    // 1: fc1 + bn1 -> h
    gemm_kernel<0><<<dim3(2, 25, BB), 256>>>(x, fc1_w, fc1_b, bn1_g, bn1_b, bn1_m, bn1_v);
    // 2: normalize rows -> sq + bf16 concat split buffers
    norm_kernel<<<BB * NN, 64>>>();
    // 3: positional embedding (K-major)
    pe_kernel<<<(NN * CC + 255) / 256, 256>>>();
    // 4: rel (symmetric upper-tri + mirror)
    gemm_kernel<1><<<dim3(25, 25, 1), 256>>>(nullptr, nullptr, nullptr, nullptr, nullptr, nullptr, nullptr);
    // 5: dist via mma.sync bf16 split (symmetric upper-tri; writes both tiles)
    dist_mma_kernel<<<dim3(25, 25, BB), 256, DSM_TOTAL>>>();
    // 6: fused top-9 + gather/max-edge -> g = [h, d]
    topk_gather_kernel<<<BB * NN, 256>>>();
    // 7: grouped conv + bn + gelu -> y
    gemm_kernel<3><<<dim3(1, 25, BB * 4), 256>>>(nullptr, gc_w, gc_b, bng_g, bng_b, bng_m, bng_v);
    // 8: fc2 + bn2 -> o
    gemm_kernel<4><<<dim3(2, 196, 1), 256>>>(nullptr, fc2_w, fc2_b, bn2_g, bn2_b, bn2_m, bn2_v);
    // 9: transpose + residual -> out
    out_kernel<<<dim3(98, 6, BB), dim3(32, 8)>>>(x, out);
}

// round 10
// speedup vs baseline: 1.1868x; 1.1868x over previous
#include <cuda_runtime.h>
#include <cuda_bf16.h>
#include <math.h>
#include <stdint.h>

// Problem constants (fixed shapes from setup_inputs)
#define BB  8
#define CC  192
#define HH  56
#define WW  56
#define NN  3136            // H*W
#define CC2 384             // 2*C
#define CG  96              // C2/4
#define KNB 9               // K_NEIGHBORS
#define BNEPS 1e-5f
#define KTOT 576            // 3*CC  (hi|hi|lo concat)
#define KSLAB 64
#define NSLABS 9            // KTOT/KSLAB

// ---------------- scratch (static device globals; no runtime alloc) --------
__device__ float d_R   [56 * 56];                          // rel position table
__device__ float d_h   [(size_t)BB * NN * CC];             // 19.3 MB
__device__ __nv_bfloat16 d_xa[(size_t)BB * NN * KTOT];     // 28.9 MB  [hi|hi|lo]
__device__ __nv_bfloat16 d_xb[(size_t)BB * NN * KTOT];     // 28.9 MB  [hi|lo|hi]
__device__ float d_sq  [BB * NN];
__device__ float d_dist[(size_t)BB * NN * NN];             // 314.7 MB
__device__ float d_gbuf[(size_t)BB * NN * CC2];            // 38.6 MB
__device__ float d_ybuf[(size_t)BB * NN * CC2];            // 38.6 MB
__device__ float d_obuf[(size_t)BB * NN * CC];             // 19.3 MB

__device__ __forceinline__ uint32_t smem_u32(const void* p) {
    uint32_t a;
    asm("{ .reg .u64 t; cvta.to.shared.u64 t, %1; cvt.u32.u64 %0, t; }"
        : "=r"(a) : "l"(p));
    return a;
}

// ---------------- rel position table: R[a][b] = -2/C * emb(a).emb(b) --------
__global__ void rel_table_kernel() {
    int p = blockIdx.x * 128 + threadIdx.x;
    if (p >= 56 * 56) return;
    int a = p / 56, b = p - (p / 56) * 56;
    float s = 0.0f;
#pragma unroll 1
    for (int i = 0; i < 48; i++) {
        float wv = expf(-logf(10000.0f) * (float)i / 48.0f);
        float sa, ca, sb, cb;
        sincosf((float)a * wv, &sa, &ca);
        sincosf((float)b * wv, &sb, &cb);
        s += sa * sb + ca * cb;
    }
    d_R[p] = (-2.0f / (float)CC) * s;
}

// ---------------- 128x128x16 double-buffered SGEMM (modes 0,3,4) -----------
// C(m,n) = sum_k A(m,k) * B(n,k)
// MODE 0: fc1   A = x_b (K-major), bias+BN1 -> d_h
// MODE 3: group A = d_gbuf slice row-major, B = gc_w[g], bias+BN+GELU -> d_ybuf
// MODE 4: fc2   A = d_ybuf row-major, bias+BN2 -> d_obuf
template <int MODE>
__global__ void __launch_bounds__(256, 2)
gemm_kernel(const float* __restrict__ Ain, const float* __restrict__ Bin,
            const float* __restrict__ q0, const float* __restrict__ q1,
            const float* __restrict__ q2, const float* __restrict__ q3,
            const float* __restrict__ q4)
{
    constexpr bool AKM = (MODE == 0);     // A stored K-major

    int M, Nc, K, lda, ldb;
    const float* A;
    const float* B;
    const int bz = blockIdx.z;

    if (MODE == 0) {
        A = Ain + (size_t)bz * CC * NN;  B = Bin;
        M = NN; Nc = CC; K = CC; lda = NN; ldb = CC;
    } else if (MODE == 3) {
        int b = bz >> 2, g = bz & 3;
        A = d_gbuf + (size_t)b * NN * CC2 + g * CG;
        B = Bin + (size_t)g * CG * CG;
        M = NN; Nc = CG; K = CG; lda = CC2; ldb = CG;
    } else {
        A = d_ybuf; B = Bin;
        M = BB * NN; Nc = CC; K = CC2; lda = CC2; ldb = CC2;
    }

    __shared__ float As[2][16][128];
    __shared__ float Bs[2][16][128];

    const int tid = threadIdx.x;
    const int tx = tid & 15;
    const int ty = tid >> 4;
    const int m0 = blockIdx.y * 128;
    const int n0 = blockIdx.x * 128;

    const float* aptr0;
    const float* aptr1;
    int a_km_k = 0, a_km_m = 0;
    int a_rm_r = 0, a_rm_kq = 0;
    if (AKM) {
        a_km_k = tid >> 5;
        a_km_m = (tid & 31) * 4;
        int mc = min(m0 + a_km_m, M - 4);
        aptr0 = A + (size_t)a_km_k * lda + mc;
        aptr1 = A + (size_t)(a_km_k + 8) * lda + mc;
    } else {
        a_rm_r  = tid >> 1;
        a_rm_kq = (tid & 1) * 8;
        int rc = min(m0 + a_rm_r, M - 1);
        aptr0 = A + (size_t)rc * lda + a_rm_kq;
        aptr1 = aptr0 + 4;
    }
    const int b_rm_r  = tid >> 1;
    const int b_rm_kq = (tid & 1) * 8;
    const float* bptr0 = B + (size_t)min(n0 + b_rm_r, Nc - 1) * ldb + b_rm_kq;
    const float* bptr1 = bptr0 + 4;

    float4 ra0, ra1, rb0, rb1;
    ra0 = *reinterpret_cast<const float4*>(aptr0);
    ra1 = *reinterpret_cast<const float4*>(aptr1);
    rb0 = *reinterpret_cast<const float4*>(bptr0);
    rb1 = *reinterpret_cast<const float4*>(bptr1);
    if (AKM) {
        *reinterpret_cast<float4*>(&As[0][a_km_k][a_km_m])     = ra0;
        *reinterpret_cast<float4*>(&As[0][a_km_k + 8][a_km_m]) = ra1;
    } else {
        As[0][a_rm_kq + 0][a_rm_r] = ra0.x; As[0][a_rm_kq + 1][a_rm_r] = ra0.y;
        As[0][a_rm_kq + 2][a_rm_r] = ra0.z; As[0][a_rm_kq + 3][a_rm_r] = ra0.w;
        As[0][a_rm_kq + 4][a_rm_r] = ra1.x; As[0][a_rm_kq + 5][a_rm_r] = ra1.y;
        As[0][a_rm_kq + 6][a_rm_r] = ra1.z; As[0][a_rm_kq + 7][a_rm_r] = ra1.w;
    }
    Bs[0][b_rm_kq + 0][b_rm_r] = rb0.x; Bs[0][b_rm_kq + 1][b_rm_r] = rb0.y;
    Bs[0][b_rm_kq + 2][b_rm_r] = rb0.z; Bs[0][b_rm_kq + 3][b_rm_r] = rb0.w;
    Bs[0][b_rm_kq + 4][b_rm_r] = rb1.x; Bs[0][b_rm_kq + 5][b_rm_r] = rb1.y;
    Bs[0][b_rm_kq + 6][b_rm_r] = rb1.z; Bs[0][b_rm_kq + 7][b_rm_r] = rb1.w;
    __syncthreads();

    float acc[8][8];
#pragma unroll
    for (int i = 0; i < 8; i++)
#pragma unroll
        for (int j = 0; j < 8; j++) acc[i][j] = 0.0f;

    const int T = K >> 4;
    for (int t = 0; t < T; t++) {
        const int cur = t & 1;
        if (t + 1 < T) {
            if (AKM) { aptr0 += (size_t)16 * lda; aptr1 += (size_t)16 * lda; }
            else     { aptr0 += 16;               aptr1 += 16; }
            bptr0 += 16; bptr1 += 16;
            ra0 = *reinterpret_cast<const float4*>(aptr0);
            ra1 = *reinterpret_cast<const float4*>(aptr1);
            rb0 = *reinterpret_cast<const float4*>(bptr0);
            rb1 = *reinterpret_cast<const float4*>(bptr1);
        }
#pragma unroll
        for (int kk = 0; kk < 16; kk++) {
            float af[8], bf[8];
            *reinterpret_cast<float4*>(&af[0]) = *reinterpret_cast<const float4*>(&As[cur][kk][ty * 4]);
            *reinterpret_cast<float4*>(&af[4]) = *reinterpret_cast<const float4*>(&As[cur][kk][64 + ty * 4]);
            *reinterpret_cast<float4*>(&bf[0]) = *reinterpret_cast<const float4*>(&Bs[cur][kk][tx * 4]);
            *reinterpret_cast<float4*>(&bf[4]) = *reinterpret_cast<const float4*>(&Bs[cur][kk][64 + tx * 4]);
#pragma unroll
            for (int i = 0; i < 8; i++)
#pragma unroll
                for (int j = 0; j < 8; j++) acc[i][j] += af[i] * bf[j];
        }
        if (t + 1 < T) {
            const int nxt = cur ^ 1;
            if (AKM) {
                *reinterpret_cast<float4*>(&As[nxt][a_km_k][a_km_m])     = ra0;
                *reinterpret_cast<float4*>(&As[nxt][a_km_k + 8][a_km_m]) = ra1;
            } else {
                As[nxt][a_rm_kq + 0][a_rm_r] = ra0.x; As[nxt][a_rm_kq + 1][a_rm_r] = ra0.y;
                As[nxt][a_rm_kq + 2][a_rm_r] = ra0.z; As[nxt][a_rm_kq + 3][a_rm_r] = ra0.w;
                As[nxt][a_rm_kq + 4][a_rm_r] = ra1.x; As[nxt][a_rm_kq + 5][a_rm_r] = ra1.y;
                As[nxt][a_rm_kq + 6][a_rm_r] = ra1.z; As[nxt][a_rm_kq + 7][a_rm_r] = ra1.w;
            }
            Bs[nxt][b_rm_kq + 0][b_rm_r] = rb0.x; Bs[nxt][b_rm_kq + 1][b_rm_r] = rb0.y;
            Bs[nxt][b_rm_kq + 2][b_rm_r] = rb0.z; Bs[nxt][b_rm_kq + 3][b_rm_r] = rb0.w;
            Bs[nxt][b_rm_kq + 4][b_rm_r] = rb1.x; Bs[nxt][b_rm_kq + 5][b_rm_r] = rb1.y;
            Bs[nxt][b_rm_kq + 6][b_rm_r] = rb1.z; Bs[nxt][b_rm_kq + 7][b_rm_r] = rb1.w;
        }
        __syncthreads();
    }

    int rows[8], cols[8];
#pragma unroll
    for (int i = 0; i < 4; i++) {
        rows[i]     = m0 + ty * 4 + i;
        rows[i + 4] = m0 + 64 + ty * 4 + i;
        cols[i]     = n0 + tx * 4 + i;
        cols[i + 4] = n0 + 64 + tx * 4 + i;
    }

    if (MODE == 0) {
        float sc[8], bi[8];
#pragma unroll
        for (int j = 0; j < 8; j++) {
            if (cols[j] < Nc) {
                float s = q1[cols[j]] * rsqrtf(q4[cols[j]] + BNEPS);
                sc[j] = s;
                bi[j] = (q0[cols[j]] - q3[cols[j]]) * s + q2[cols[j]];
            } else { sc[j] = 0.f; bi[j] = 0.f; }
        }
        float* hb = d_h + (size_t)bz * NN * CC;
#pragma unroll
        for (int i = 0; i < 8; i++) {
            if (rows[i] >= M) continue;
#pragma unroll
            for (int j = 0; j < 8; j++)
                if (cols[j] < Nc)
                    hb[(size_t)rows[i] * CC + cols[j]] = acc[i][j] * sc[j] + bi[j];
        }
    } else if (MODE == 3) {
        int b = bz >> 2, g = bz & 3;
        float sc[8], bi[8];
        int ch[8];
#pragma unroll
        for (int j = 0; j < 8; j++) {
            ch[j] = g * CG + cols[j];
            if (cols[j] < Nc) {
                float s = q1[ch[j]] * rsqrtf(q4[ch[j]] + BNEPS);
                sc[j] = s;
                bi[j] = (q0[ch[j]] - q3[ch[j]]) * s + q2[ch[j]];
            } else { sc[j] = 0.f; bi[j] = 0.f; }
        }
        float* yb = d_ybuf + (size_t)b * NN * CC2;
#pragma unroll
        for (int i = 0; i < 8; i++) {
            if (rows[i] >= M) continue;
#pragma unroll
            for (int j = 0; j < 8; j++)
                if (cols[j] < Nc) {
                    float t2 = acc[i][j] * sc[j] + bi[j];
                    yb[(size_t)rows[i] * CC2 + ch[j]] = t2 * normcdff(t2);
                }
        }
    } else { // MODE 4
        float sc[8], bi[8];
#pragma unroll
        for (int j = 0; j < 8; j++) {
            if (cols[j] < Nc) {
                float s = q1[cols[j]] * rsqrtf(q4[cols[j]] + BNEPS);
                sc[j] = s;
                bi[j] = (q0[cols[j]] - q3[cols[j]]) * s + q2[cols[j]];
            } else { sc[j] = 0.f; bi[j] = 0.f; }
        }
#pragma unroll
        for (int i = 0; i < 8; i++) {
            if (rows[i] >= M) continue;
#pragma unroll
            for (int j = 0; j < 8; j++)
                if (cols[j] < Nc)
                    d_obuf[(size_t)rows[i] * CC + cols[j]] = acc[i][j] * sc[j] + bi[j];
        }
    }
}

// ---------------- L2 normalize + sq + bf16 hi/lo concat buffers --------------
__global__ void norm_kernel() {
    int row = blockIdx.x;
    const float* hr = d_h + (size_t)row * CC;
    int t = threadIdx.x;                    // 64 threads
    float a0 = hr[t], a1 = hr[t + 64], a2 = hr[t + 128];
    float ss = a0 * a0 + a1 * a1 + a2 * a2;
#pragma unroll
    for (int o = 16; o > 0; o >>= 1) ss += __shfl_down_sync(0xffffffffu, ss, o);
    __shared__ float w1[2], w2[2];
    if ((t & 31) == 0) w1[t >> 5] = ss;
    __syncthreads();
    float norm = sqrtf(w1[0] + w1[1]);
    float inv = 1.0f / fmaxf(norm, 1e-12f);
    float xv[3] = { a0 * inv, a1 * inv, a2 * inv };
    float s2 = xv[0] * xv[0] + xv[1] * xv[1] + xv[2] * xv[2];
#pragma unroll
    for (int o = 16; o > 0; o >>= 1) s2 += __shfl_down_sync(0xffffffffu, s2, o);
    if ((t & 31) == 0) w2[t >> 5] = s2;

    __nv_bfloat16* xa = d_xa + (size_t)row * KTOT;
    __nv_bfloat16* xb = d_xb + (size_t)row * KTOT;
#pragma unroll
    for (int e = 0; e < 3; e++) {
        int c = t + e * 64;
        float x = xv[e];
        __nv_bfloat16 h = __float2bfloat16(x);
        __nv_bfloat16 l = __float2bfloat16(x - __bfloat162float(h));
        xa[c]       = h;  xa[192 + c] = h;  xa[384 + c] = l;
        xb[c]       = h;  xb[192 + c] = l;  xb[384 + c] = h;
    }
    __syncthreads();
    if (t == 0) d_sq[row] = w2[0] + w2[1];
}

// ---------------- dist via mma.sync bf16 (K=576 concat split) ----------------
// CTA 128x128, 8 warps 4(m)x2(n), warp tile 32x64, K-slab 64, cp.async dbl-buf.
// rel via 56x56 smem table lookups (rel[n][m] = R[yy_n][yy_m] + R[xx_n][xx_m]).
#define SROW 144                       // smem tile row bytes (72 bf16: 64 + 8 pad)
#define TILE_B (128 * SROW)            // 18432
#define SM_R   0                       // 12544 B
#define SM_IDX 12544                   // 2048 B (yyR,xxR,yyC,xxC int[128])
#define SM_BUF 14592
#define DS_STRIDE 132
#define DSM_TOTAL (SM_BUF + 4 * TILE_B)   // 88320
__global__ void __launch_bounds__(256)
dist_mma_kernel() {
    if (blockIdx.y > blockIdx.x) return;
    extern __shared__ char smem[];
    const int tid = threadIdx.x, w = tid >> 5, lane = tid & 31;
    const int b = blockIdx.z;
    const int m0 = blockIdx.y * 128, n0 = blockIdx.x * 128;

    float* Rs  = reinterpret_cast<float*>(smem + SM_R);
    int*   yyR = reinterpret_cast<int*>(smem + SM_IDX);
    int*   xxR = yyR + 128;
    int*   yyC = yyR + 256;
    int*   xxC = yyR + 384;

    for (int i = tid; i < 56 * 56; i += 256) Rs[i] = d_R[i];
    if (tid < 128) {
        int rg = min(m0 + tid, NN - 1);
        yyR[tid] = rg / 56; xxR[tid] = rg - (rg / 56) * 56;
        int cg = min(n0 + tid, NN - 1);
        yyC[tid] = cg / 56; xxC[tid] = cg - (cg / 56) * 56;
    }

    const uint32_t sbuf = smem_u32(smem + SM_BUF);
    const uint32_t sAq[2] = { sbuf, sbuf + TILE_B };
    const uint32_t sBq[2] = { sbuf + 2 * TILE_B, sbuf + 3 * TILE_B };

    const __nv_bfloat16* baseA = d_xa + (size_t)b * NN * KTOT;
    const __nv_bfloat16* baseB = d_xb + (size_t)b * NN * KTOT;

    auto issue = [&](int s) {
        const int k0b = s * KSLAB * 2;
        const uint32_t dA = sAq[s & 1], dB = sBq[s & 1];
#pragma unroll
        for (int c = 0; c < 4; c++) {
            int ch = tid + c * 256;
            int row = ch >> 3, cg = (ch & 7) * 16;
            const char* ga = (const char*)(baseA + (size_t)min(m0 + row, NN - 1) * KTOT) + k0b + cg;
            const char* gb = (const char*)(baseB + (size_t)min(n0 + row, NN - 1) * KTOT) + k0b + cg;
            uint32_t off = row * SROW + cg;
            asm volatile("cp.async.cg.shared.global [%0], [%1], 16;" :: "r"(dA + off), "l"(ga));
            asm volatile("cp.async.cg.shared.global [%0], [%1], 16;" :: "r"(dB + off), "l"(gb));
        }
        asm volatile("cp.async.commit_group;" ::: "memory");
    };

    issue(0);
    issue(1);

    float acc[2][8][4];
#pragma unroll
    for (int i = 0; i < 2; i++)
#pragma unroll
        for (int j = 0; j < 8; j++)
#pragma unroll
            for (int k = 0; k < 4; k++) acc[i][j][k] = 0.0f;

    const int wm = w & 3;                         // rows wm*32
    const int wn = w >> 2;                        // cols wn*64
    const int aRow  = lane & 15;
    const int aColB = ((lane >> 4) * 8) * 2;
    const int bNr   = ((lane >> 4) << 3) + (lane & 7);
    const int bColB = (((lane >> 3) & 1) * 8) * 2;

    for (int s = 0; s < NSLABS; s++) {
        if (s < NSLABS - 1)
            asm volatile("cp.async.wait_group 1;" ::: "memory");
        else
            asm volatile("cp.async.wait_group 0;" ::: "memory");
        __syncthreads();
        const uint32_t cA = sAq[s & 1], cB = sBq[s & 1];
#pragma unroll
        for (int kk = 0; kk < 4; kk++) {
            const int k0b = kk * 32;
            uint32_t af[2][4];
#pragma unroll
            for (int mi = 0; mi < 2; mi++) {
                uint32_t addr = cA + (wm * 32 + mi * 16 + aRow) * SROW + k0b + aColB;
                asm volatile(
                    "ldmatrix.sync.aligned.m8n8.x4.shared.b16 {%0,%1,%2,%3}, [%4];"
                    : "=r"(af[mi][0]), "=r"(af[mi][1]), "=r"(af[mi][2]), "=r"(af[mi][3])
                    : "r"(addr));
            }
            uint32_t bfv[4][4];
#pragma unroll
            for (int nb = 0; nb < 4; nb++) {
                uint32_t addr = cB + (wn * 64 + nb * 16 + bNr) * SROW + k0b + bColB;
                asm volatile(
                    "ldmatrix.sync.aligned.m8n8.x4.shared.b16 {%0,%1,%2,%3}, [%4];"
                    : "=r"(bfv[nb][0]), "=r"(bfv[nb][1]), "=r"(bfv[nb][2]), "=r"(bfv[nb][3])
                    : "r"(addr));
            }
#pragma unroll
            for (int mi = 0; mi < 2; mi++)
#pragma unroll
                for (int ni = 0; ni < 8; ni++) {
                    uint32_t b0 = bfv[ni >> 1][(ni & 1) * 2 + 0];
                    uint32_t b1 = bfv[ni >> 1][(ni & 1) * 2 + 1];
                    asm volatile(
                        "mma.sync.aligned.m16n8k16.row.col.f32.bf16.bf16.f32 "
                        "{%0,%1,%2,%3}, {%4,%5,%6,%7}, {%8,%9}, {%0,%1,%2,%3};"
                        : "+f"(acc[mi][ni][0]), "+f"(acc[mi][ni][1]),
                          "+f"(acc[mi][ni][2]), "+f"(acc[mi][ni][3])
                        : "r"(af[mi][0]), "r"(af[mi][1]), "r"(af[mi][2]), "r"(af[mi][3]),
                          "r"(b0), "r"(b1));
                }
        }
        __syncthreads();
        if (s + 2 < NSLABS) issue(s + 2);
    }

    // ---- stage C to smem [128][DS_STRIDE] (overlaps tile buffers, post-sync)
    float* Ds = reinterpret_cast<float*>(smem + SM_BUF);
#pragma unroll
    for (int mi = 0; mi < 2; mi++) {
        int r0 = wm * 32 + mi * 16 + (lane >> 2);
        int c0 = wn * 64 + (lane & 3) * 2;
#pragma unroll
        for (int ni = 0; ni < 8; ni++) {
            int cc = c0 + ni * 8;
            Ds[r0 * DS_STRIDE + cc]           = acc[mi][ni][0];
            Ds[r0 * DS_STRIDE + cc + 1]       = acc[mi][ni][1];
            Ds[(r0 + 8) * DS_STRIDE + cc]     = acc[mi][ni][2];
            Ds[(r0 + 8) * DS_STRIDE + cc + 1] = acc[mi][ni][3];
        }
    }
    __syncthreads();

    float* db = d_dist + (size_t)b * NN * NN;
    const float* sqb = d_sq + b * NN;

    // phase 1: mirror tile; lane = row (coalesced stores, 4-way LDS worst case)
    if (blockIdx.x != blockIdx.y) {
        for (int cl = w; cl < 128; cl += 8) {
            int m = n0 + cl;
            if (m >= NN) continue;
            float* dbm = db + (size_t)m * NN;
            const int yc = yyC[cl], xc = xxC[cl];
#pragma unroll
            for (int rq = 0; rq < 4; rq++) {
                int rl = rq * 32 + lane;
                int rg = m0 + rl;
                if (rg >= NN) continue;
                float v = Ds[rl * DS_STRIDE + cl];
                float relv = Rs[yyR[rl] * 56 + yc] + Rs[xxR[rl] * 56 + xc];
                dbm[rg] = sqb[rg] - 2.0f * v + relv;
            }
        }
    }

    // phase 2: normal tile (row-coalesced float4)
#pragma unroll 1
    for (int it = 0; it < 16; it++) {
        int f = tid + it * 256;
        int rl = f >> 5, c4 = f & 31;
        int rg = m0 + rl;
        if (rg >= NN) continue;
        int gc = n0 + c4 * 4;
        float4 dv = *reinterpret_cast<const float4*>(&Ds[rl * DS_STRIDE + c4 * 4]);
        const int yr = yyR[rl] * 56, xr = xxR[rl] * 56;
        float* dd = db + (size_t)rg * NN;
        if (gc + 3 < NN) {
            float4 sq4 = *reinterpret_cast<const float4*>(sqb + gc);
            float4 o;
            o.x = sq4.x - 2.0f * dv.x + Rs[yr + yyC[c4 * 4 + 0]] + Rs[xr + xxC[c4 * 4 + 0]];
            o.y = sq4.y - 2.0f * dv.y + Rs[yr + yyC[c4 * 4 + 1]] + Rs[xr + xxC[c4 * 4 + 1]];
            o.z = sq4.z - 2.0f * dv.z + Rs[yr + yyC[c4 * 4 + 2]] + Rs[xr + xxC[c4 * 4 + 2]];
            o.w = sq4.w - 2.0f * dv.w + Rs[yr + yyC[c4 * 4 + 3]] + Rs[xr + xxC[c4 * 4 + 3]];
            *reinterpret_cast<float4*>(&dd[gc]) = o;
        } else {
            float dvv[4] = { dv.x, dv.y, dv.z, dv.w };
#pragma unroll
            for (int i = 0; i < 4; i++)
                if (gc + i < NN)
                    dd[gc + i] = sqb[gc + i] - 2.0f * dvv[i]
                        + Rs[yr + yyC[c4 * 4 + i]] + Rs[xr + xxC[c4 * 4 + i]];
        }
    }
}

// ---------------- fused top-9 + gather/max-edge ------------------------------
__global__ void __launch_bounds__(256) topk_gather_kernel() {
    const int row = blockIdx.x;
    const int b = row / NN, n = row % NN;
    const float4* dr4 = reinterpret_cast<const float4*>(
        d_dist + (size_t)b * NN * NN + (size_t)n * NN);

    float tv[KNB];
    int   ti[KNB];
#pragma unroll
    for (int q = 0; q < KNB; q++) { tv[q] = INFINITY; ti[q] = 0x7fffffff; }

    for (int i4 = threadIdx.x; i4 < NN / 4; i4 += 256) {
        float4 v4 = dr4[i4];
        const int mb = i4 * 4;
        float vv[4] = { v4.x, v4.y, v4.z, v4.w };
#pragma unroll
        for (int c = 0; c < 4; c++) {
            float v = vv[c];
            if (v < tv[KNB - 1]) {
                tv[KNB - 1] = v; ti[KNB - 1] = mb + c;
#pragma unroll
                for (int q = KNB - 1; q > 0; q--) {
                    if (tv[q] < tv[q - 1]) {
                        float fv = tv[q]; tv[q] = tv[q - 1]; tv[q - 1] = fv;
                        int   fi = ti[q]; ti[q] = ti[q - 1]; ti[q - 1] = fi;
                    }
                }
            }
        }
    }

    __shared__ float sv[256 * KNB];
    __shared__ int   si[256 * KNB];
#pragma unroll
    for (int q = 0; q < KNB; q++) { sv[threadIdx.x * KNB + q] = tv[q]; si[threadIdx.x * KNB + q] = ti[q]; }

    for (int stride = 128; stride >= 1; stride >>= 1) {
        __syncthreads();
        if (threadIdx.x < (unsigned)stride) {
            float* Av = &sv[threadIdx.x * KNB];
            int*   Ai = &si[threadIdx.x * KNB];
            float* Bv = &sv[(threadIdx.x + stride) * KNB];
            int*   Bi = &si[(threadIdx.x + stride) * KNB];
            float ov[KNB]; int oi[KNB];
            int ia = 0, ib = 0;
#pragma unroll
            for (int q = 0; q < KNB; q++) {
                float va = (ia < KNB) ? Av[ia] : INFINITY;
                float vb = (ib < KNB) ? Bv[ib] : INFINITY;
                int xa = (ia < KNB) ? Ai[ia] : 0x7fffffff;
                int xb = (ib < KNB) ? Bi[ib] : 0x7fffffff;
                bool takeA = (va < vb) || (va == vb && xa < xb);
                ov[q] = takeA ? va : vb;
                oi[q] = takeA ? xa : xb;
                if (takeA) ia++; else ib++;
            }
#pragma unroll
            for (int q = 0; q < KNB; q++) { Av[q] = ov[q]; Ai[q] = oi[q]; }
        }
    }
    __syncthreads();

    if (threadIdx.x < CC) {
        const int c = threadIdx.x;
        const float* hb = d_h + (size_t)b * NN * CC;
        float hn = d_h[(size_t)row * CC + c];
        float mx = -INFINITY;
#pragma unroll
        for (int j = 0; j < KNB; j++)
            mx = fmaxf(mx, hb[(size_t)si[j] * CC + c] - hn);
        d_gbuf[(size_t)row * CC2 + c]      = hn;
        d_gbuf[(size_t)row * CC2 + CC + c] = mx;
    }
}

// ---------------- transpose (B,N,C)->(B,C,N) + residual ---------------------
__global__ void out_kernel(const float* __restrict__ x, float* __restrict__ out) {
    __shared__ float tile[32][33];
    const int b = blockIdx.z;
    const int n0 = blockIdx.x * 32, c0 = blockIdx.y * 32;
    const int tx = threadIdx.x, ty = threadIdx.y;
#pragma unroll
    for (int i = 0; i < 32; i += 8)
        tile[ty + i][tx] = d_obuf[((size_t)b * NN + n0 + ty + i) * CC + c0 + tx];
    __syncthreads();
#pragma unroll
    for (int i = 0; i < 32; i += 8) {
        int c = c0 + ty + i, n = n0 + tx;
        size_t o = ((size_t)b * CC + c) * NN + n;
        out[o] = tile[tx][ty + i] + x[o];
    }
}

// ---------------- launch ----------------------------------------------------
extern "C" void kernel_launch(void* const* d_in, const int* in_sizes, int n_in,
                              void* d_out, int out_size)
{
    (void)in_sizes; (void)n_in; (void)out_size;
    const float* x     = (const float*)d_in[0];
    const float* fc1_w = (const float*)d_in[1];
    const float* fc1_b = (const float*)d_in[2];
    const float* bn1_g = (const float*)d_in[3];
    const float* bn1_b = (const float*)d_in[4];
    const float* bn1_m = (const float*)d_in[5];
    const float* bn1_v = (const float*)d_in[6];
    const float* gc_w  = (const float*)d_in[7];
    const float* gc_b  = (const float*)d_in[8];
    const float* bng_g = (const float*)d_in[9];
    const float* bng_b = (const float*)d_in[10];
    const float* bng_m = (const float*)d_in[11];
    const float* bng_v = (const float*)d_in[12];
    const float* fc2_w = (const float*)d_in[13];
    const float* fc2_b = (const float*)d_in[14];
    const float* bn2_g = (const float*)d_in[15];
    const float* bn2_b = (const float*)d_in[16];
    const float* bn2_m = (const float*)d_in[17];
    const float* bn2_v = (const float*)d_in[18];
    float* out = (float*)d_out;

    cudaFuncSetAttribute(dist_mma_kernel,
                         cudaFuncAttributeMaxDynamicSharedMemorySize, DSM_TOTAL);

    // 1: rel position table (56x56)
    rel_table_kernel<<<25, 128>>>();
    // 2: fc1 + bn1 -> h
    gemm_kernel<0><<<dim3(2, 25, BB), 256>>>(x, fc1_w, fc1_b, bn1_g, bn1_b, bn1_m, bn1_v);
    // 3: normalize rows -> sq + bf16 concat split buffers
    norm_kernel<<<BB * NN, 64>>>();
    // 4: dist via mma.sync bf16 split + rel table lookups  [ncu capture slot]
    dist_mma_kernel<<<dim3(25, 25, BB), 256, DSM_TOTAL>>>();
    // 5: fused top-9 + gather/max-edge -> g = [h, d]
    topk_gather_kernel<<<BB * NN, 256>>>();
    // 6: grouped conv + bn + gelu -> y
    gemm_kernel<3><<<dim3(1, 25, BB * 4), 256>>>(nullptr, gc_w, gc_b, bng_g, bng_b, bng_m, bng_v);
    // 7: fc2 + bn2 -> o
    gemm_kernel<4><<<dim3(2, 196, 1), 256>>>(nullptr, fc2_w, fc2_b, bn2_g, bn2_b, bn2_m, bn2_v);
    // 8: transpose + residual -> out
    out_kernel<<<dim3(98, 6, BB), dim3(32, 8)>>>(x, out);
}

// round 11
// speedup vs baseline: 1.2016x; 1.0125x over previous
#include <cuda_runtime.h>
#include <cuda_bf16.h>
#include <math.h>
#include <stdint.h>

// Problem constants (fixed shapes from setup_inputs)
#define BB  8
#define CC  192
#define HH  56
#define WW  56
#define NN  3136            // H*W
#define CC2 384             // 2*C
#define CG  96              // C2/4
#define KNB 9               // K_NEIGHBORS
#define BNEPS 1e-5f
#define KTOT 576            // 3*CC  (hi|hi|lo concat)
#define KSLAB 64
#define NSLABS 9            // KTOT/KSLAB

// ---------------- scratch (static device globals; no runtime alloc) --------
__device__ float d_R   [56 * 56];                          // rel position table
__device__ float d_h   [(size_t)BB * NN * CC];             // 19.3 MB
__device__ __nv_bfloat16 d_xa[(size_t)BB * NN * KTOT];     // 28.9 MB  [hi|hi|lo]
__device__ __nv_bfloat16 d_xb[(size_t)BB * NN * KTOT];     // 28.9 MB  [hi|lo|hi]
__device__ float d_sq  [BB * NN];
__device__ float d_dist[(size_t)BB * NN * NN];             // 314.7 MB
__device__ float d_gbuf[(size_t)BB * NN * CC2];            // 38.6 MB
__device__ float d_ybuf[(size_t)BB * NN * CC2];            // 38.6 MB
__device__ float d_obuf[(size_t)BB * NN * CC];             // 19.3 MB

__device__ __forceinline__ uint32_t smem_u32(const void* p) {
    uint32_t a;
    asm("{ .reg .u64 t; cvta.to.shared.u64 t, %1; cvt.u32.u64 %0, t; }"
        : "=r"(a) : "l"(p));
    return a;
}

// ---------------- rel position table: R[a][b] = -2/C * emb(a).emb(b) --------
__global__ void rel_table_kernel() {
    int p = blockIdx.x * 128 + threadIdx.x;
    if (p >= 56 * 56) return;
    int a = p / 56, b = p - (p / 56) * 56;
    float s = 0.0f;
#pragma unroll 1
    for (int i = 0; i < 48; i++) {
        float wv = expf(-logf(10000.0f) * (float)i / 48.0f);
        float sa, ca, sb, cb;
        sincosf((float)a * wv, &sa, &ca);
        sincosf((float)b * wv, &sb, &cb);
        s += sa * sb + ca * cb;
    }
    d_R[p] = (-2.0f / (float)CC) * s;
}

// ---------------- 128x128x16 double-buffered SGEMM (modes 0,3,4) -----------
template <int MODE>
__global__ void __launch_bounds__(256, 2)
gemm_kernel(const float* __restrict__ Ain, const float* __restrict__ Bin,
            const float* __restrict__ q0, const float* __restrict__ q1,
            const float* __restrict__ q2, const float* __restrict__ q3,
            const float* __restrict__ q4)
{
    constexpr bool AKM = (MODE == 0);     // A stored K-major

    int M, Nc, K, lda, ldb;
    const float* A;
    const float* B;
    const int bz = blockIdx.z;

    if (MODE == 0) {
        A = Ain + (size_t)bz * CC * NN;  B = Bin;
        M = NN; Nc = CC; K = CC; lda = NN; ldb = CC;
    } else if (MODE == 3) {
        int b = bz >> 2, g = bz & 3;
        A = d_gbuf + (size_t)b * NN * CC2 + g * CG;
        B = Bin + (size_t)g * CG * CG;
        M = NN; Nc = CG; K = CG; lda = CC2; ldb = CG;
    } else {
        A = d_ybuf; B = Bin;
        M = BB * NN; Nc = CC; K = CC2; lda = CC2; ldb = CC2;
    }

    __shared__ float As[2][16][128];
    __shared__ float Bs[2][16][128];

    const int tid = threadIdx.x;
    const int tx = tid & 15;
    const int ty = tid >> 4;
    const int m0 = blockIdx.y * 128;
    const int n0 = blockIdx.x * 128;

    const float* aptr0;
    const float* aptr1;
    int a_km_k = 0, a_km_m = 0;
    int a_rm_r = 0, a_rm_kq = 0;
    if (AKM) {
        a_km_k = tid >> 5;
        a_km_m = (tid & 31) * 4;
        int mc = min(m0 + a_km_m, M - 4);
        aptr0 = A + (size_t)a_km_k * lda + mc;
        aptr1 = A + (size_t)(a_km_k + 8) * lda + mc;
    } else {
        a_rm_r  = tid >> 1;
        a_rm_kq = (tid & 1) * 8;
        int rc = min(m0 + a_rm_r, M - 1);
        aptr0 = A + (size_t)rc * lda + a_rm_kq;
        aptr1 = aptr0 + 4;
    }
    const int b_rm_r  = tid >> 1;
    const int b_rm_kq = (tid & 1) * 8;
    const float* bptr0 = B + (size_t)min(n0 + b_rm_r, Nc - 1) * ldb + b_rm_kq;
    const float* bptr1 = bptr0 + 4;

    float4 ra0, ra1, rb0, rb1;
    ra0 = *reinterpret_cast<const float4*>(aptr0);
    ra1 = *reinterpret_cast<const float4*>(aptr1);
    rb0 = *reinterpret_cast<const float4*>(bptr0);
    rb1 = *reinterpret_cast<const float4*>(bptr1);
    if (AKM) {
        *reinterpret_cast<float4*>(&As[0][a_km_k][a_km_m])     = ra0;
        *reinterpret_cast<float4*>(&As[0][a_km_k + 8][a_km_m]) = ra1;
    } else {
        As[0][a_rm_kq + 0][a_rm_r] = ra0.x; As[0][a_rm_kq + 1][a_rm_r] = ra0.y;
        As[0][a_rm_kq + 2][a_rm_r] = ra0.z; As[0][a_rm_kq + 3][a_rm_r] = ra0.w;
        As[0][a_rm_kq + 4][a_rm_r] = ra1.x; As[0][a_rm_kq + 5][a_rm_r] = ra1.y;
        As[0][a_rm_kq + 6][a_rm_r] = ra1.z; As[0][a_rm_kq + 7][a_rm_r] = ra1.w;
    }
    Bs[0][b_rm_kq + 0][b_rm_r] = rb0.x; Bs[0][b_rm_kq + 1][b_rm_r] = rb0.y;
    Bs[0][b_rm_kq + 2][b_rm_r] = rb0.z; Bs[0][b_rm_kq + 3][b_rm_r] = rb0.w;
    Bs[0][b_rm_kq + 4][b_rm_r] = rb1.x; Bs[0][b_rm_kq + 5][b_rm_r] = rb1.y;
    Bs[0][b_rm_kq + 6][b_rm_r] = rb1.z; Bs[0][b_rm_kq + 7][b_rm_r] = rb1.w;
    __syncthreads();

    float acc[8][8];
#pragma unroll
    for (int i = 0; i < 8; i++)
#pragma unroll
        for (int j = 0; j < 8; j++) acc[i][j] = 0.0f;

    const int T = K >> 4;
    for (int t = 0; t < T; t++) {
        const int cur = t & 1;
        if (t + 1 < T) {
            if (AKM) { aptr0 += (size_t)16 * lda; aptr1 += (size_t)16 * lda; }
            else     { aptr0 += 16;               aptr1 += 16; }
            bptr0 += 16; bptr1 += 16;
            ra0 = *reinterpret_cast<const float4*>(aptr0);
            ra1 = *reinterpret_cast<const float4*>(aptr1);
            rb0 = *reinterpret_cast<const float4*>(bptr0);
            rb1 = *reinterpret_cast<const float4*>(bptr1);
        }
#pragma unroll
        for (int kk = 0; kk < 16; kk++) {
            float af[8], bf[8];
            *reinterpret_cast<float4*>(&af[0]) = *reinterpret_cast<const float4*>(&As[cur][kk][ty * 4]);
            *reinterpret_cast<float4*>(&af[4]) = *reinterpret_cast<const float4*>(&As[cur][kk][64 + ty * 4]);
            *reinterpret_cast<float4*>(&bf[0]) = *reinterpret_cast<const float4*>(&Bs[cur][kk][tx * 4]);
            *reinterpret_cast<float4*>(&bf[4]) = *reinterpret_cast<const float4*>(&Bs[cur][kk][64 + tx * 4]);
#pragma unroll
            for (int i = 0; i < 8; i++)
#pragma unroll
                for (int j = 0; j < 8; j++) acc[i][j] += af[i] * bf[j];
        }
        if (t + 1 < T) {
            const int nxt = cur ^ 1;
            if (AKM) {
                *reinterpret_cast<float4*>(&As[nxt][a_km_k][a_km_m])     = ra0;
                *reinterpret_cast<float4*>(&As[nxt][a_km_k + 8][a_km_m]) = ra1;
            } else {
                As[nxt][a_rm_kq + 0][a_rm_r] = ra0.x; As[nxt][a_rm_kq + 1][a_rm_r] = ra0.y;
                As[nxt][a_rm_kq + 2][a_rm_r] = ra0.z; As[nxt][a_rm_kq + 3][a_rm_r] = ra0.w;
                As[nxt][a_rm_kq + 4][a_rm_r] = ra1.x; As[nxt][a_rm_kq + 5][a_rm_r] = ra1.y;
                As[nxt][a_rm_kq + 6][a_rm_r] = ra1.z; As[nxt][a_rm_kq + 7][a_rm_r] = ra1.w;
            }
            Bs[nxt][b_rm_kq + 0][b_rm_r] = rb0.x; Bs[nxt][b_rm_kq + 1][b_rm_r] = rb0.y;
            Bs[nxt][b_rm_kq + 2][b_rm_r] = rb0.z; Bs[nxt][b_rm_kq + 3][b_rm_r] = rb0.w;
            Bs[nxt][b_rm_kq + 4][b_rm_r] = rb1.x; Bs[nxt][b_rm_kq + 5][b_rm_r] = rb1.y;
            Bs[nxt][b_rm_kq + 6][b_rm_r] = rb1.z; Bs[nxt][b_rm_kq + 7][b_rm_r] = rb1.w;
        }
        __syncthreads();
    }

    int rows[8], cols[8];
#pragma unroll
    for (int i = 0; i < 4; i++) {
        rows[i]     = m0 + ty * 4 + i;
        rows[i + 4] = m0 + 64 + ty * 4 + i;
        cols[i]     = n0 + tx * 4 + i;
        cols[i + 4] = n0 + 64 + tx * 4 + i;
    }

    if (MODE == 0) {
        float sc[8], bi[8];
#pragma unroll
        for (int j = 0; j < 8; j++) {
            if (cols[j] < Nc) {
                float s = q1[cols[j]] * rsqrtf(q4[cols[j]] + BNEPS);
                sc[j] = s;
                bi[j] = (q0[cols[j]] - q3[cols[j]]) * s + q2[cols[j]];
            } else { sc[j] = 0.f; bi[j] = 0.f; }
        }
        float* hb = d_h + (size_t)bz * NN * CC;
#pragma unroll
        for (int i = 0; i < 8; i++) {
            if (rows[i] >= M) continue;
#pragma unroll
            for (int j = 0; j < 8; j++)
                if (cols[j] < Nc)
                    hb[(size_t)rows[i] * CC + cols[j]] = acc[i][j] * sc[j] + bi[j];
        }
    } else if (MODE == 3) {
        int b = bz >> 2, g = bz & 3;
        float sc[8], bi[8];
        int ch[8];
#pragma unroll
        for (int j = 0; j < 8; j++) {
            ch[j] = g * CG + cols[j];
            if (cols[j] < Nc) {
                float s = q1[ch[j]] * rsqrtf(q4[ch[j]] + BNEPS);
                sc[j] = s;
                bi[j] = (q0[ch[j]] - q3[ch[j]]) * s + q2[ch[j]];
            } else { sc[j] = 0.f; bi[j] = 0.f; }
        }
        float* yb = d_ybuf + (size_t)b * NN * CC2;
#pragma unroll
        for (int i = 0; i < 8; i++) {
            if (rows[i] >= M) continue;
#pragma unroll
            for (int j = 0; j < 8; j++)
                if (cols[j] < Nc) {
                    float t2 = acc[i][j] * sc[j] + bi[j];
                    yb[(size_t)rows[i] * CC2 + ch[j]] = t2 * normcdff(t2);
                }
        }
    } else { // MODE 4
        float sc[8], bi[8];
#pragma unroll
        for (int j = 0; j < 8; j++) {
            if (cols[j] < Nc) {
                float s = q1[cols[j]] * rsqrtf(q4[cols[j]] + BNEPS);
                sc[j] = s;
                bi[j] = (q0[cols[j]] - q3[cols[j]]) * s + q2[cols[j]];
            } else { sc[j] = 0.f; bi[j] = 0.f; }
        }
#pragma unroll
        for (int i = 0; i < 8; i++) {
            if (rows[i] >= M) continue;
#pragma unroll
            for (int j = 0; j < 8; j++)
                if (cols[j] < Nc)
                    d_obuf[(size_t)rows[i] * CC + cols[j]] = acc[i][j] * sc[j] + bi[j];
        }
    }
}

// ---------------- L2 normalize + sq + bf16 hi/lo concat buffers --------------
__global__ void norm_kernel() {
    int row = blockIdx.x;
    const float* hr = d_h + (size_t)row * CC;
    int t = threadIdx.x;                    // 64 threads
    float a0 = hr[t], a1 = hr[t + 64], a2 = hr[t + 128];
    float ss = a0 * a0 + a1 * a1 + a2 * a2;
#pragma unroll
    for (int o = 16; o > 0; o >>= 1) ss += __shfl_down_sync(0xffffffffu, ss, o);
    __shared__ float w1[2], w2[2];
    if ((t & 31) == 0) w1[t >> 5] = ss;
    __syncthreads();
    float norm = sqrtf(w1[0] + w1[1]);
    float inv = 1.0f / fmaxf(norm, 1e-12f);
    float xv[3] = { a0 * inv, a1 * inv, a2 * inv };
    float s2 = xv[0] * xv[0] + xv[1] * xv[1] + xv[2] * xv[2];
#pragma unroll
    for (int o = 16; o > 0; o >>= 1) s2 += __shfl_down_sync(0xffffffffu, s2, o);
    if ((t & 31) == 0) w2[t >> 5] = s2;

    __nv_bfloat16* xa = d_xa + (size_t)row * KTOT;
    __nv_bfloat16* xb = d_xb + (size_t)row * KTOT;
#pragma unroll
    for (int e = 0; e < 3; e++) {
        int c = t + e * 64;
        float x = xv[e];
        __nv_bfloat16 h = __float2bfloat16(x);
        __nv_bfloat16 l = __float2bfloat16(x - __bfloat162float(h));
        xa[c]       = h;  xa[192 + c] = h;  xa[384 + c] = l;
        xb[c]       = h;  xb[192 + c] = l;  xb[384 + c] = h;
    }
    __syncthreads();
    if (t == 0) d_sq[row] = w2[0] + w2[1];
}

// ---------------- dist via mma.sync bf16 (K=576 concat split) ----------------
// CTA 128x128, 8 warps 4(m)x2(n), warp tile 32x64, K-slab 64, cp.async dbl-buf.
// rel via 56x56 smem table; C staging stride 133 (odd) => conflict-free epilogue.
#define SROW 144                       // smem tile row bytes (72 bf16: 64 + 8 pad)
#define TILE_B (128 * SROW)            // 18432
#define SM_R   0                       // 12544 B
#define SM_IDX 12544                   // 2048 B (yyR,xxR,yyC,xxC int[128])
#define SM_BUF 14592
#define DS_STRIDE 133
#define DSM_TOTAL (SM_BUF + 4 * TILE_B)   // 88320 (>= SM_BUF + 128*133*4)
__global__ void __launch_bounds__(256)
dist_mma_kernel() {
    if (blockIdx.y > blockIdx.x) return;
    extern __shared__ char smem[];
    const int tid = threadIdx.x, w = tid >> 5, lane = tid & 31;
    const int b = blockIdx.z;
    const int m0 = blockIdx.y * 128, n0 = blockIdx.x * 128;

    float* Rs  = reinterpret_cast<float*>(smem + SM_R);
    int*   yyR = reinterpret_cast<int*>(smem + SM_IDX);
    int*   xxR = yyR + 128;
    int*   yyC = yyR + 256;
    int*   xxC = yyR + 384;

    for (int i = tid; i < 56 * 56; i += 256) Rs[i] = d_R[i];
    if (tid < 128) {
        int rg = min(m0 + tid, NN - 1);
        yyR[tid] = rg / 56; xxR[tid] = rg - (rg / 56) * 56;
        int cg = min(n0 + tid, NN - 1);
        yyC[tid] = cg / 56; xxC[tid] = cg - (cg / 56) * 56;
    }

    const uint32_t sbuf = smem_u32(smem + SM_BUF);
    const uint32_t sAq[2] = { sbuf, sbuf + TILE_B };
    const uint32_t sBq[2] = { sbuf + 2 * TILE_B, sbuf + 3 * TILE_B };

    const __nv_bfloat16* baseA = d_xa + (size_t)b * NN * KTOT;
    const __nv_bfloat16* baseB = d_xb + (size_t)b * NN * KTOT;

    auto issue = [&](int s) {
        const int k0b = s * KSLAB * 2;
        const uint32_t dA = sAq[s & 1], dB = sBq[s & 1];
#pragma unroll
        for (int c = 0; c < 4; c++) {
            int ch = tid + c * 256;
            int row = ch >> 3, cg = (ch & 7) * 16;
            const char* ga = (const char*)(baseA + (size_t)min(m0 + row, NN - 1) * KTOT) + k0b + cg;
            const char* gb = (const char*)(baseB + (size_t)min(n0 + row, NN - 1) * KTOT) + k0b + cg;
            uint32_t off = row * SROW + cg;
            asm volatile("cp.async.cg.shared.global [%0], [%1], 16;" :: "r"(dA + off), "l"(ga));
            asm volatile("cp.async.cg.shared.global [%0], [%1], 16;" :: "r"(dB + off), "l"(gb));
        }
        asm volatile("cp.async.commit_group;" ::: "memory");
    };

    issue(0);
    issue(1);

    float acc[2][8][4];
#pragma unroll
    for (int i = 0; i < 2; i++)
#pragma unroll
        for (int j = 0; j < 8; j++)
#pragma unroll
            for (int k = 0; k < 4; k++) acc[i][j][k] = 0.0f;

    const int wm = w & 3;                         // rows wm*32
    const int wn = w >> 2;                        // cols wn*64
    const int aRow  = lane & 15;
    const int aColB = ((lane >> 4) * 8) * 2;
    const int bNr   = ((lane >> 4) << 3) + (lane & 7);
    const int bColB = (((lane >> 3) & 1) * 8) * 2;

    for (int s = 0; s < NSLABS; s++) {
        if (s < NSLABS - 1)
            asm volatile("cp.async.wait_group 1;" ::: "memory");
        else
            asm volatile("cp.async.wait_group 0;" ::: "memory");
        __syncthreads();
        const uint32_t cA = sAq[s & 1], cB = sBq[s & 1];
#pragma unroll
        for (int kk = 0; kk < 4; kk++) {
            const int k0b = kk * 32;
            uint32_t af[2][4];
#pragma unroll
            for (int mi = 0; mi < 2; mi++) {
                uint32_t addr = cA + (wm * 32 + mi * 16 + aRow) * SROW + k0b + aColB;
                asm volatile(
                    "ldmatrix.sync.aligned.m8n8.x4.shared.b16 {%0,%1,%2,%3}, [%4];"
                    : "=r"(af[mi][0]), "=r"(af[mi][1]), "=r"(af[mi][2]), "=r"(af[mi][3])
                    : "r"(addr));
            }
            uint32_t bfv[4][4];
#pragma unroll
            for (int nb = 0; nb < 4; nb++) {
                uint32_t addr = cB + (wn * 64 + nb * 16 + bNr) * SROW + k0b + bColB;
                asm volatile(
                    "ldmatrix.sync.aligned.m8n8.x4.shared.b16 {%0,%1,%2,%3}, [%4];"
                    : "=r"(bfv[nb][0]), "=r"(bfv[nb][1]), "=r"(bfv[nb][2]), "=r"(bfv[nb][3])
                    : "r"(addr));
            }
#pragma unroll
            for (int mi = 0; mi < 2; mi++)
#pragma unroll
                for (int ni = 0; ni < 8; ni++) {
                    uint32_t b0 = bfv[ni >> 1][(ni & 1) * 2 + 0];
                    uint32_t b1 = bfv[ni >> 1][(ni & 1) * 2 + 1];
                    asm volatile(
                        "mma.sync.aligned.m16n8k16.row.col.f32.bf16.bf16.f32 "
                        "{%0,%1,%2,%3}, {%4,%5,%6,%7}, {%8,%9}, {%0,%1,%2,%3};"
                        : "+f"(acc[mi][ni][0]), "+f"(acc[mi][ni][1]),
                          "+f"(acc[mi][ni][2]), "+f"(acc[mi][ni][3])
                        : "r"(af[mi][0]), "r"(af[mi][1]), "r"(af[mi][2]), "r"(af[mi][3]),
                          "r"(b0), "r"(b1));
                }
        }
        __syncthreads();
        if (s + 2 < NSLABS) issue(s + 2);
    }

    // ---- stage C to smem [128][DS_STRIDE=133] (odd stride: conflict-free reads)
    float* Ds = reinterpret_cast<float*>(smem + SM_BUF);
#pragma unroll
    for (int mi = 0; mi < 2; mi++) {
        int r0 = wm * 32 + mi * 16 + (lane >> 2);
        int c0 = wn * 64 + (lane & 3) * 2;
#pragma unroll
        for (int ni = 0; ni < 8; ni++) {
            int cc = c0 + ni * 8;
            Ds[r0 * DS_STRIDE + cc]           = acc[mi][ni][0];
            Ds[r0 * DS_STRIDE + cc + 1]       = acc[mi][ni][1];
            Ds[(r0 + 8) * DS_STRIDE + cc]     = acc[mi][ni][2];
            Ds[(r0 + 8) * DS_STRIDE + cc + 1] = acc[mi][ni][3];
        }
    }
    __syncthreads();

    float* db = d_dist + (size_t)b * NN * NN;
    const float* sqb = d_sq + b * NN;

    // phase 1: mirror tile; lane = row (coalesced stores, conflict-free LDS)
    if (blockIdx.x != blockIdx.y) {
        for (int cl = w; cl < 128; cl += 8) {
            int m = n0 + cl;
            if (m >= NN) continue;
            float* dbm = db + (size_t)m * NN;
            const int yc = yyC[cl], xc = xxC[cl];
#pragma unroll
            for (int rq = 0; rq < 4; rq++) {
                int rl = rq * 32 + lane;
                int rg = m0 + rl;
                if (rg >= NN) continue;
                float v = Ds[rl * DS_STRIDE + cl];
                float relv = Rs[yyR[rl] * 56 + yc] + Rs[xxR[rl] * 56 + xc];
                dbm[rg] = sqb[rg] - 2.0f * v + relv;
            }
        }
    }

    // phase 2: normal tile; thread = column, sweep rows (conflict-free LDS,
    // coalesced scalar stores, broadcast row-index reads)
    {
        const int c = tid & 127;
        const int rh = (tid >> 7) * 64;
        const int gc = n0 + c;
        if (gc < NN) {
            const float sqc = sqb[gc];
            const int yc = yyC[c], xc = xxC[c];
#pragma unroll 1
            for (int r = 0; r < 64; r++) {
                int rl = rh + r;
                int rg = m0 + rl;
                if (rg >= NN) break;
                float v = Ds[rl * DS_STRIDE + c];
                float relv = Rs[yyR[rl] * 56 + yc] + Rs[xxR[rl] * 56 + xc];
                db[(size_t)rg * NN + gc] = sqc - 2.0f * v + relv;
            }
        }
    }
}

// ---------------- fused top-9 + gather/max-edge ------------------------------
__global__ void __launch_bounds__(256) topk_gather_kernel() {
    const int row = blockIdx.x;
    const int b = row / NN, n = row % NN;
    const float4* dr4 = reinterpret_cast<const float4*>(
        d_dist + (size_t)b * NN * NN + (size_t)n * NN);

    float tv[KNB];
    int   ti[KNB];
#pragma unroll
    for (int q = 0; q < KNB; q++) { tv[q] = INFINITY; ti[q] = 0x7fffffff; }

    for (int i4 = threadIdx.x; i4 < NN / 4; i4 += 256) {
        float4 v4 = dr4[i4];
        const int mb = i4 * 4;
        float vv[4] = { v4.x, v4.y, v4.z, v4.w };
#pragma unroll
        for (int c = 0; c < 4; c++) {
            float v = vv[c];
            if (v < tv[KNB - 1]) {
                tv[KNB - 1] = v; ti[KNB - 1] = mb + c;
#pragma unroll
                for (int q = KNB - 1; q > 0; q--) {
                    if (tv[q] < tv[q - 1]) {
                        float fv = tv[q]; tv[q] = tv[q - 1]; tv[q - 1] = fv;
                        int   fi = ti[q]; ti[q] = ti[q - 1]; ti[q - 1] = fi;
                    }
                }
            }
        }
    }

    __shared__ float sv[256 * KNB];
    __shared__ int   si[256 * KNB];
#pragma unroll
    for (int q = 0; q < KNB; q++) { sv[threadIdx.x * KNB + q] = tv[q]; si[threadIdx.x * KNB + q] = ti[q]; }

    for (int stride = 128; stride >= 1; stride >>= 1) {
        __syncthreads();
        if (threadIdx.x < (unsigned)stride) {
            float* Av = &sv[threadIdx.x * KNB];
            int*   Ai = &si[threadIdx.x * KNB];
            float* Bv = &sv[(threadIdx.x + stride) * KNB];
            int*   Bi = &si[(threadIdx.x + stride) * KNB];
            float ov[KNB]; int oi[KNB];
            int ia = 0, ib = 0;
#pragma unroll
            for (int q = 0; q < KNB; q++) {
                float va = (ia < KNB) ? Av[ia] : INFINITY;
                float vb = (ib < KNB) ? Bv[ib] : INFINITY;
                int xa = (ia < KNB) ? Ai[ia] : 0x7fffffff;
                int xb = (ib < KNB) ? Bi[ib] : 0x7fffffff;
                bool takeA = (va < vb) || (va == vb && xa < xb);
                ov[q] = takeA ? va : vb;
                oi[q] = takeA ? xa : xb;
                if (takeA) ia++; else ib++;
            }
#pragma unroll
            for (int q = 0; q < KNB; q++) { Av[q] = ov[q]; Ai[q] = oi[q]; }
        }
    }
    __syncthreads();

    if (threadIdx.x < CC) {
        const int c = threadIdx.x;
        const float* hb = d_h + (size_t)b * NN * CC;
        float hn = d_h[(size_t)row * CC + c];
        float mx = -INFINITY;
#pragma unroll
        for (int j = 0; j < KNB; j++)
            mx = fmaxf(mx, hb[(size_t)si[j] * CC + c] - hn);
        d_gbuf[(size_t)row * CC2 + c]      = hn;
        d_gbuf[(size_t)row * CC2 + CC + c] = mx;
    }
}

// ---------------- transpose (B,N,C)->(B,C,N) + residual ---------------------
__global__ void out_kernel(const float* __restrict__ x, float* __restrict__ out) {
    __shared__ float tile[32][33];
    const int b = blockIdx.z;
    const int n0 = blockIdx.x * 32, c0 = blockIdx.y * 32;
    const int tx = threadIdx.x, ty = threadIdx.y;
#pragma unroll
    for (int i = 0; i < 32; i += 8)
        tile[ty + i][tx] = d_obuf[((size_t)b * NN + n0 + ty + i) * CC + c0 + tx];
    __syncthreads();
#pragma unroll
    for (int i = 0; i < 32; i += 8) {
        int c = c0 + ty + i, n = n0 + tx;
        size_t o = ((size_t)b * CC + c) * NN + n;
        out[o] = tile[tx][ty + i] + x[o];
    }
}

// ---------------- launch ----------------------------------------------------
extern "C" void kernel_launch(void* const* d_in, const int* in_sizes, int n_in,
                              void* d_out, int out_size)
{
    (void)in_sizes; (void)n_in; (void)out_size;
    const float* x     = (const float*)d_in[0];
    const float* fc1_w = (const float*)d_in[1];
    const float* fc1_b = (const float*)d_in[2];
    const float* bn1_g = (const float*)d_in[3];
    const float* bn1_b = (const float*)d_in[4];
    const float* bn1_m = (const float*)d_in[5];
    const float* bn1_v = (const float*)d_in[6];
    const float* gc_w  = (const float*)d_in[7];
    const float* gc_b  = (const float*)d_in[8];
    const float* bng_g = (const float*)d_in[9];
    const float* bng_b = (const float*)d_in[10];
    const float* bng_m = (const float*)d_in[11];
    const float* bng_v = (const float*)d_in[12];
    const float* fc2_w = (const float*)d_in[13];
    const float* fc2_b = (const float*)d_in[14];
    const float* bn2_g = (const float*)d_in[15];
    const float* bn2_b = (const float*)d_in[16];
    const float* bn2_m = (const float*)d_in[17];
    const float* bn2_v = (const float*)d_in[18];
    float* out = (float*)d_out;

    cudaFuncSetAttribute(dist_mma_kernel,
                         cudaFuncAttributeMaxDynamicSharedMemorySize, DSM_TOTAL);

    // 1: rel position table (56x56)
    rel_table_kernel<<<25, 128>>>();
    // 2: fc1 + bn1 -> h
    gemm_kernel<0><<<dim3(2, 25, BB), 256>>>(x, fc1_w, fc1_b, bn1_g, bn1_b, bn1_m, bn1_v);
    // 3: normalize rows -> sq + bf16 concat split buffers
    norm_kernel<<<BB * NN, 64>>>();
    // 4: dist via mma.sync bf16 split + rel table lookups  [ncu capture slot]
    dist_mma_kernel<<<dim3(25, 25, BB), 256, DSM_TOTAL>>>();
    // 5: fused top-9 + gather/max-edge -> g = [h, d]
    topk_gather_kernel<<<BB * NN, 256>>>();
    // 6: grouped conv + bn + gelu -> y
    gemm_kernel<3><<<dim3(1, 25, BB * 4), 256>>>(nullptr, gc_w, gc_b, bng_g, bng_b, bng_m, bng_v);
    // 7: fc2 + bn2 -> o
    gemm_kernel<4><<<dim3(2, 196, 1), 256>>>(nullptr, fc2_w, fc2_b, bn2_g, bn2_b, bn2_m, bn2_v);
    // 8: transpose + residual -> out
    out_kernel<<<dim3(98, 6, BB), dim3(32, 8)>>>(x, out);
}

// round 12
// speedup vs baseline: 1.2042x; 1.0022x over previous
#include <cuda_runtime.h>
#include <cuda_bf16.h>
#include <math.h>
#include <stdint.h>

// Problem constants (fixed shapes from setup_inputs)
#define BB  8
#define CC  192
#define HH  56
#define WW  56
#define NN  3136            // H*W
#define CC2 384             // 2*C
#define CG  96              // C2/4
#define KNB 9               // K_NEIGHBORS
#define BNEPS 1e-5f
#define KTOT 576            // 3*CC  (hi|hi|lo concat)
#define KSLAB 64
#define NSLABS 9            // KTOT/KSLAB

// ---------------- scratch (static device globals; no runtime alloc) --------
__device__ float d_R   [56 * 56];                          // rel position table
__device__ float d_h   [(size_t)BB * NN * CC];             // 19.3 MB
__device__ __nv_bfloat16 d_xa[(size_t)BB * NN * KTOT];     // 28.9 MB  [hi|hi|lo]
__device__ __nv_bfloat16 d_xb[(size_t)BB * NN * KTOT];     // 28.9 MB  [hi|lo|hi]
__device__ float d_sq  [BB * NN];
__device__ float d_dist[(size_t)BB * NN * NN];             // 314.7 MB
__device__ float d_gbuf[(size_t)BB * NN * CC2];            // 38.6 MB
__device__ float d_ybuf[(size_t)BB * NN * CC2];            // 38.6 MB
__device__ float d_obuf[(size_t)BB * NN * CC];             // 19.3 MB

__device__ __forceinline__ uint32_t smem_u32(const void* p) {
    uint32_t a;
    asm("{ .reg .u64 t; cvta.to.shared.u64 t, %1; cvt.u32.u64 %0, t; }"
        : "=r"(a) : "l"(p));
    return a;
}

// ---------------- rel position table: R[a][b] = -2/C * emb(a).emb(b) --------
__global__ void rel_table_kernel() {
    int p = blockIdx.x * 128 + threadIdx.x;
    if (p >= 56 * 56) return;
    int a = p / 56, b = p - (p / 56) * 56;
    float s = 0.0f;
#pragma unroll 1
    for (int i = 0; i < 48; i++) {
        float wv = expf(-logf(10000.0f) * (float)i / 48.0f);
        float sa, ca, sb, cb;
        sincosf((float)a * wv, &sa, &ca);
        sincosf((float)b * wv, &sb, &cb);
        s += sa * sb + ca * cb;
    }
    d_R[p] = (-2.0f / (float)CC) * s;
}

// ---------------- 128x128x16 double-buffered SGEMM (modes 0,3,4) -----------
template <int MODE>
__global__ void __launch_bounds__(256, 2)
gemm_kernel(const float* __restrict__ Ain, const float* __restrict__ Bin,
            const float* __restrict__ q0, const float* __restrict__ q1,
            const float* __restrict__ q2, const float* __restrict__ q3,
            const float* __restrict__ q4)
{
    constexpr bool AKM = (MODE == 0);     // A stored K-major

    int M, Nc, K, lda, ldb;
    const float* A;
    const float* B;
    const int bz = blockIdx.z;

    if (MODE == 0) {
        A = Ain + (size_t)bz * CC * NN;  B = Bin;
        M = NN; Nc = CC; K = CC; lda = NN; ldb = CC;
    } else if (MODE == 3) {
        int b = bz >> 2, g = bz & 3;
        A = d_gbuf + (size_t)b * NN * CC2 + g * CG;
        B = Bin + (size_t)g * CG * CG;
        M = NN; Nc = CG; K = CG; lda = CC2; ldb = CG;
    } else {
        A = d_ybuf; B = Bin;
        M = BB * NN; Nc = CC; K = CC2; lda = CC2; ldb = CC2;
    }

    __shared__ float As[2][16][128];
    __shared__ float Bs[2][16][128];

    const int tid = threadIdx.x;
    const int tx = tid & 15;
    const int ty = tid >> 4;
    const int m0 = blockIdx.y * 128;
    const int n0 = blockIdx.x * 128;

    const float* aptr0;
    const float* aptr1;
    int a_km_k = 0, a_km_m = 0;
    int a_rm_r = 0, a_rm_kq = 0;
    if (AKM) {
        a_km_k = tid >> 5;
        a_km_m = (tid & 31) * 4;
        int mc = min(m0 + a_km_m, M - 4);
        aptr0 = A + (size_t)a_km_k * lda + mc;
        aptr1 = A + (size_t)(a_km_k + 8) * lda + mc;
    } else {
        a_rm_r  = tid >> 1;
        a_rm_kq = (tid & 1) * 8;
        int rc = min(m0 + a_rm_r, M - 1);
        aptr0 = A + (size_t)rc * lda + a_rm_kq;
        aptr1 = aptr0 + 4;
    }
    const int b_rm_r  = tid >> 1;
    const int b_rm_kq = (tid & 1) * 8;
    const float* bptr0 = B + (size_t)min(n0 + b_rm_r, Nc - 1) * ldb + b_rm_kq;
    const float* bptr1 = bptr0 + 4;

    float4 ra0, ra1, rb0, rb1;
    ra0 = *reinterpret_cast<const float4*>(aptr0);
    ra1 = *reinterpret_cast<const float4*>(aptr1);
    rb0 = *reinterpret_cast<const float4*>(bptr0);
    rb1 = *reinterpret_cast<const float4*>(bptr1);
    if (AKM) {
        *reinterpret_cast<float4*>(&As[0][a_km_k][a_km_m])     = ra0;
        *reinterpret_cast<float4*>(&As[0][a_km_k + 8][a_km_m]) = ra1;
    } else {
        As[0][a_rm_kq + 0][a_rm_r] = ra0.x; As[0][a_rm_kq + 1][a_rm_r] = ra0.y;
        As[0][a_rm_kq + 2][a_rm_r] = ra0.z; As[0][a_rm_kq + 3][a_rm_r] = ra0.w;
        As[0][a_rm_kq + 4][a_rm_r] = ra1.x; As[0][a_rm_kq + 5][a_rm_r] = ra1.y;
        As[0][a_rm_kq + 6][a_rm_r] = ra1.z; As[0][a_rm_kq + 7][a_rm_r] = ra1.w;
    }
    Bs[0][b_rm_kq + 0][b_rm_r] = rb0.x; Bs[0][b_rm_kq + 1][b_rm_r] = rb0.y;
    Bs[0][b_rm_kq + 2][b_rm_r] = rb0.z; Bs[0][b_rm_kq + 3][b_rm_r] = rb0.w;
    Bs[0][b_rm_kq + 4][b_rm_r] = rb1.x; Bs[0][b_rm_kq + 5][b_rm_r] = rb1.y;
    Bs[0][b_rm_kq + 6][b_rm_r] = rb1.z; Bs[0][b_rm_kq + 7][b_rm_r] = rb1.w;
    __syncthreads();

    float acc[8][8];
#pragma unroll
    for (int i = 0; i < 8; i++)
#pragma unroll
        for (int j = 0; j < 8; j++) acc[i][j] = 0.0f;

    const int T = K >> 4;
    for (int t = 0; t < T; t++) {
        const int cur = t & 1;
        if (t + 1 < T) {
            if (AKM) { aptr0 += (size_t)16 * lda; aptr1 += (size_t)16 * lda; }
            else     { aptr0 += 16;               aptr1 += 16; }
            bptr0 += 16; bptr1 += 16;
            ra0 = *reinterpret_cast<const float4*>(aptr0);
            ra1 = *reinterpret_cast<const float4*>(aptr1);
            rb0 = *reinterpret_cast<const float4*>(bptr0);
            rb1 = *reinterpret_cast<const float4*>(bptr1);
        }
#pragma unroll
        for (int kk = 0; kk < 16; kk++) {
            float af[8], bf[8];
            *reinterpret_cast<float4*>(&af[0]) = *reinterpret_cast<const float4*>(&As[cur][kk][ty * 4]);
            *reinterpret_cast<float4*>(&af[4]) = *reinterpret_cast<const float4*>(&As[cur][kk][64 + ty * 4]);
            *reinterpret_cast<float4*>(&bf[0]) = *reinterpret_cast<const float4*>(&Bs[cur][kk][tx * 4]);
            *reinterpret_cast<float4*>(&bf[4]) = *reinterpret_cast<const float4*>(&Bs[cur][kk][64 + tx * 4]);
#pragma unroll
            for (int i = 0; i < 8; i++)
#pragma unroll
                for (int j = 0; j < 8; j++) acc[i][j] += af[i] * bf[j];
        }
        if (t + 1 < T) {
            const int nxt = cur ^ 1;
            if (AKM) {
                *reinterpret_cast<float4*>(&As[nxt][a_km_k][a_km_m])     = ra0;
                *reinterpret_cast<float4*>(&As[nxt][a_km_k + 8][a_km_m]) = ra1;
            } else {
                As[nxt][a_rm_kq + 0][a_rm_r] = ra0.x; As[nxt][a_rm_kq + 1][a_rm_r] = ra0.y;
                As[nxt][a_rm_kq + 2][a_rm_r] = ra0.z; As[nxt][a_rm_kq + 3][a_rm_r] = ra0.w;
                As[nxt][a_rm_kq + 4][a_rm_r] = ra1.x; As[nxt][a_rm_kq + 5][a_rm_r] = ra1.y;
                As[nxt][a_rm_kq + 6][a_rm_r] = ra1.z; As[nxt][a_rm_kq + 7][a_rm_r] = ra1.w;
            }
            Bs[nxt][b_rm_kq + 0][b_rm_r] = rb0.x; Bs[nxt][b_rm_kq + 1][b_rm_r] = rb0.y;
            Bs[nxt][b_rm_kq + 2][b_rm_r] = rb0.z; Bs[nxt][b_rm_kq + 3][b_rm_r] = rb0.w;
            Bs[nxt][b_rm_kq + 4][b_rm_r] = rb1.x; Bs[nxt][b_rm_kq + 5][b_rm_r] = rb1.y;
            Bs[nxt][b_rm_kq + 6][b_rm_r] = rb1.z; Bs[nxt][b_rm_kq + 7][b_rm_r] = rb1.w;
        }
        __syncthreads();
    }

    int rows[8], cols[8];
#pragma unroll
    for (int i = 0; i < 4; i++) {
        rows[i]     = m0 + ty * 4 + i;
        rows[i + 4] = m0 + 64 + ty * 4 + i;
        cols[i]     = n0 + tx * 4 + i;
        cols[i + 4] = n0 + 64 + tx * 4 + i;
    }

    if (MODE == 0) {
        float sc[8], bi[8];
#pragma unroll
        for (int j = 0; j < 8; j++) {
            if (cols[j] < Nc) {
                float s = q1[cols[j]] * rsqrtf(q4[cols[j]] + BNEPS);
                sc[j] = s;
                bi[j] = (q0[cols[j]] - q3[cols[j]]) * s + q2[cols[j]];
            } else { sc[j] = 0.f; bi[j] = 0.f; }
        }
        float* hb = d_h + (size_t)bz * NN * CC;
#pragma unroll
        for (int i = 0; i < 8; i++) {
            if (rows[i] >= M) continue;
#pragma unroll
            for (int j = 0; j < 8; j++)
                if (cols[j] < Nc)
                    hb[(size_t)rows[i] * CC + cols[j]] = acc[i][j] * sc[j] + bi[j];
        }
    } else if (MODE == 3) {
        int b = bz >> 2, g = bz & 3;
        float sc[8], bi[8];
        int ch[8];
#pragma unroll
        for (int j = 0; j < 8; j++) {
            ch[j] = g * CG + cols[j];
            if (cols[j] < Nc) {
                float s = q1[ch[j]] * rsqrtf(q4[ch[j]] + BNEPS);
                sc[j] = s;
                bi[j] = (q0[ch[j]] - q3[ch[j]]) * s + q2[ch[j]];
            } else { sc[j] = 0.f; bi[j] = 0.f; }
        }
        float* yb = d_ybuf + (size_t)b * NN * CC2;
#pragma unroll
        for (int i = 0; i < 8; i++) {
            if (rows[i] >= M) continue;
#pragma unroll
            for (int j = 0; j < 8; j++)
                if (cols[j] < Nc) {
                    float t2 = acc[i][j] * sc[j] + bi[j];
                    yb[(size_t)rows[i] * CC2 + ch[j]] = t2 * normcdff(t2);
                }
        }
    } else { // MODE 4
        float sc[8], bi[8];
#pragma unroll
        for (int j = 0; j < 8; j++) {
            if (cols[j] < Nc) {
                float s = q1[cols[j]] * rsqrtf(q4[cols[j]] + BNEPS);
                sc[j] = s;
                bi[j] = (q0[cols[j]] - q3[cols[j]]) * s + q2[cols[j]];
            } else { sc[j] = 0.f; bi[j] = 0.f; }
        }
#pragma unroll
        for (int i = 0; i < 8; i++) {
            if (rows[i] >= M) continue;
#pragma unroll
            for (int j = 0; j < 8; j++)
                if (cols[j] < Nc)
                    d_obuf[(size_t)rows[i] * CC + cols[j]] = acc[i][j] * sc[j] + bi[j];
        }
    }
}

// ---------------- L2 normalize + sq + bf16 hi/lo concat buffers --------------
__global__ void norm_kernel() {
    int row = blockIdx.x;
    const float* hr = d_h + (size_t)row * CC;
    int t = threadIdx.x;                    // 64 threads
    float a0 = hr[t], a1 = hr[t + 64], a2 = hr[t + 128];
    float ss = a0 * a0 + a1 * a1 + a2 * a2;
#pragma unroll
    for (int o = 16; o > 0; o >>= 1) ss += __shfl_down_sync(0xffffffffu, ss, o);
    __shared__ float w1[2], w2[2];
    if ((t & 31) == 0) w1[t >> 5] = ss;
    __syncthreads();
    float norm = sqrtf(w1[0] + w1[1]);
    float inv = 1.0f / fmaxf(norm, 1e-12f);
    float xv[3] = { a0 * inv, a1 * inv, a2 * inv };
    float s2 = xv[0] * xv[0] + xv[1] * xv[1] + xv[2] * xv[2];
#pragma unroll
    for (int o = 16; o > 0; o >>= 1) s2 += __shfl_down_sync(0xffffffffu, s2, o);
    if ((t & 31) == 0) w2[t >> 5] = s2;

    __nv_bfloat16* xa = d_xa + (size_t)row * KTOT;
    __nv_bfloat16* xb = d_xb + (size_t)row * KTOT;
#pragma unroll
    for (int e = 0; e < 3; e++) {
        int c = t + e * 64;
        float x = xv[e];
        __nv_bfloat16 h = __float2bfloat16(x);
        __nv_bfloat16 l = __float2bfloat16(x - __bfloat162float(h));
        xa[c]       = h;  xa[192 + c] = h;  xa[384 + c] = l;
        xb[c]       = h;  xb[192 + c] = l;  xb[384 + c] = h;
    }
    __syncthreads();
    if (t == 0) d_sq[row] = w2[0] + w2[1];
}

// ---------------- dist via mma.sync bf16 (K=576 concat split) ----------------
// CTA 128x128, 8 warps 4(m)x2(n), warp tile 32x64, K-slab 64, 3-stage cp.async
// (single __syncthreads per slab). rel via d_R global reads (L1-hot 12.5KB).
#define SROW 144                       // smem tile row bytes (72 bf16)
#define TILE_B (128 * SROW)            // 18432
#define SM_IDX 0                       // 2048 B (yyR,xxR,yyC,xxC int[128])
#define SM_BUF 2048
#define DS_STRIDE 133
#define DSM_TOTAL (SM_BUF + 6 * TILE_B)   // 112640
__global__ void __launch_bounds__(256)
dist_mma_kernel() {
    if (blockIdx.y > blockIdx.x) return;
    extern __shared__ char smem[];
    const int tid = threadIdx.x, w = tid >> 5, lane = tid & 31;
    const int b = blockIdx.z;
    const int m0 = blockIdx.y * 128, n0 = blockIdx.x * 128;

    int* yyR = reinterpret_cast<int*>(smem + SM_IDX);
    int* xxR = yyR + 128;
    int* yyC = yyR + 256;
    int* xxC = yyR + 384;
    if (tid < 128) {
        int rg = min(m0 + tid, NN - 1);
        yyR[tid] = rg / 56; xxR[tid] = rg - (rg / 56) * 56;
        int cg = min(n0 + tid, NN - 1);
        yyC[tid] = cg / 56; xxC[tid] = cg - (cg / 56) * 56;
    }

    const uint32_t sbuf = smem_u32(smem + SM_BUF);

    const __nv_bfloat16* baseA = d_xa + (size_t)b * NN * KTOT;
    const __nv_bfloat16* baseB = d_xb + (size_t)b * NN * KTOT;

    auto issue = [&](int s) {
        const int st = s % 3;
        const int k0b = s * KSLAB * 2;
        const uint32_t dA = sbuf + st * TILE_B;
        const uint32_t dB = sbuf + (3 + st) * TILE_B;
#pragma unroll
        for (int c = 0; c < 4; c++) {
            int ch = tid + c * 256;
            int row = ch >> 3, cg = (ch & 7) * 16;
            const char* ga = (const char*)(baseA + (size_t)min(m0 + row, NN - 1) * KTOT) + k0b + cg;
            const char* gb = (const char*)(baseB + (size_t)min(n0 + row, NN - 1) * KTOT) + k0b + cg;
            uint32_t off = row * SROW + cg;
            asm volatile("cp.async.cg.shared.global [%0], [%1], 16;" :: "r"(dA + off), "l"(ga));
            asm volatile("cp.async.cg.shared.global [%0], [%1], 16;" :: "r"(dB + off), "l"(gb));
        }
        asm volatile("cp.async.commit_group;" ::: "memory");
    };

    issue(0);
    issue(1);

    float acc[2][8][4];
#pragma unroll
    for (int i = 0; i < 2; i++)
#pragma unroll
        for (int j = 0; j < 8; j++)
#pragma unroll
            for (int k = 0; k < 4; k++) acc[i][j][k] = 0.0f;

    const int wm = w & 3;                         // rows wm*32
    const int wn = w >> 2;                        // cols wn*64
    const int aRow  = lane & 15;
    const int aColB = ((lane >> 4) * 8) * 2;
    const int bNr   = ((lane >> 4) << 3) + (lane & 7);
    const int bColB = (((lane >> 3) & 1) * 8) * 2;

    for (int s = 0; s < NSLABS; s++) {
        if (s < NSLABS - 1)
            asm volatile("cp.async.wait_group 1;" ::: "memory");
        else
            asm volatile("cp.async.wait_group 0;" ::: "memory");
        __syncthreads();                       // single barrier per slab
        if (s + 2 < NSLABS) issue(s + 2);      // fills buffer (s+2)%3 (free)
        const int st = s % 3;
        const uint32_t cA = sbuf + st * TILE_B;
        const uint32_t cB = sbuf + (3 + st) * TILE_B;
#pragma unroll
        for (int kk = 0; kk < 4; kk++) {
            const int k0b = kk * 32;
            uint32_t af[2][4];
#pragma unroll
            for (int mi = 0; mi < 2; mi++) {
                uint32_t addr = cA + (wm * 32 + mi * 16 + aRow) * SROW + k0b + aColB;
                asm volatile(
                    "ldmatrix.sync.aligned.m8n8.x4.shared.b16 {%0,%1,%2,%3}, [%4];"
                    : "=r"(af[mi][0]), "=r"(af[mi][1]), "=r"(af[mi][2]), "=r"(af[mi][3])
                    : "r"(addr));
            }
            uint32_t bfv[4][4];
#pragma unroll
            for (int nb = 0; nb < 4; nb++) {
                uint32_t addr = cB + (wn * 64 + nb * 16 + bNr) * SROW + k0b + bColB;
                asm volatile(
                    "ldmatrix.sync.aligned.m8n8.x4.shared.b16 {%0,%1,%2,%3}, [%4];"
                    : "=r"(bfv[nb][0]), "=r"(bfv[nb][1]), "=r"(bfv[nb][2]), "=r"(bfv[nb][3])
                    : "r"(addr));
            }
#pragma unroll
            for (int mi = 0; mi < 2; mi++)
#pragma unroll
                for (int ni = 0; ni < 8; ni++) {
                    uint32_t b0 = bfv[ni >> 1][(ni & 1) * 2 + 0];
                    uint32_t b1 = bfv[ni >> 1][(ni & 1) * 2 + 1];
                    asm volatile(
                        "mma.sync.aligned.m16n8k16.row.col.f32.bf16.bf16.f32 "
                        "{%0,%1,%2,%3}, {%4,%5,%6,%7}, {%8,%9}, {%0,%1,%2,%3};"
                        : "+f"(acc[mi][ni][0]), "+f"(acc[mi][ni][1]),
                          "+f"(acc[mi][ni][2]), "+f"(acc[mi][ni][3])
                        : "r"(af[mi][0]), "r"(af[mi][1]), "r"(af[mi][2]), "r"(af[mi][3]),
                          "r"(b0), "r"(b1));
                }
        }
        __syncthreads();   // all reads of buffer s%3 done before reuse at s+3
    }

    // ---- stage C to smem [128][133] (conflict-free reads; overlays buffers)
    float* Ds = reinterpret_cast<float*>(smem + SM_BUF);
#pragma unroll
    for (int mi = 0; mi < 2; mi++) {
        int r0 = wm * 32 + mi * 16 + (lane >> 2);
        int c0 = wn * 64 + (lane & 3) * 2;
#pragma unroll
        for (int ni = 0; ni < 8; ni++) {
            int cc = c0 + ni * 8;
            Ds[r0 * DS_STRIDE + cc]           = acc[mi][ni][0];
            Ds[r0 * DS_STRIDE + cc + 1]       = acc[mi][ni][1];
            Ds[(r0 + 8) * DS_STRIDE + cc]     = acc[mi][ni][2];
            Ds[(r0 + 8) * DS_STRIDE + cc + 1] = acc[mi][ni][3];
        }
    }
    __syncthreads();

    float* db = d_dist + (size_t)b * NN * NN;
    const float* sqb = d_sq + b * NN;

    // phase 1: mirror tile; lane = row (coalesced stores, conflict-free LDS)
    if (blockIdx.x != blockIdx.y) {
        for (int cl = w; cl < 128; cl += 8) {
            int m = n0 + cl;
            if (m >= NN) continue;
            float* dbm = db + (size_t)m * NN;
            const int yc = yyC[cl], xc = xxC[cl];
#pragma unroll
            for (int rq = 0; rq < 4; rq++) {
                int rl = rq * 32 + lane;
                int rg = m0 + rl;
                if (rg >= NN) continue;
                float v = Ds[rl * DS_STRIDE + cl];
                float relv = __ldg(&d_R[yyR[rl] * 56 + yc]) + __ldg(&d_R[xxR[rl] * 56 + xc]);
                dbm[rg] = sqb[rg] - 2.0f * v + relv;
            }
        }
    }

    // phase 2: normal tile; thread = column, sweep rows
    {
        const int c = tid & 127;
        const int rh = (tid >> 7) * 64;
        const int gc = n0 + c;
        if (gc < NN) {
            const float sqc = sqb[gc];
            const int yc = yyC[c], xc = xxC[c];
#pragma unroll 1
            for (int r = 0; r < 64; r++) {
                int rl = rh + r;
                int rg = m0 + rl;
                if (rg >= NN) break;
                float v = Ds[rl * DS_STRIDE + c];
                float relv = __ldg(&d_R[yyR[rl] * 56 + yc]) + __ldg(&d_R[xxR[rl] * 56 + xc]);
                db[(size_t)rg * NN + gc] = sqc - 2.0f * v + relv;
            }
        }
    }
}

// ---------------- fused top-9 + gather/max-edge (4 rows per block) -----------
__global__ void __launch_bounds__(256) topk_gather_kernel() {
    const int r = threadIdx.x >> 6;          // 0..3 row within block
    const int g = threadIdx.x & 63;          // 0..63 lane within row group
    const int row = blockIdx.x * 4 + r;      // global row (b*N + n)
    const int b = row / NN, n = row % NN;
    const float4* dr4 = reinterpret_cast<const float4*>(
        d_dist + (size_t)b * NN * NN + (size_t)n * NN);

    float tv[KNB];
    int   ti[KNB];
#pragma unroll
    for (int q = 0; q < KNB; q++) { tv[q] = INFINITY; ti[q] = 0x7fffffff; }

    for (int i4 = g; i4 < NN / 4; i4 += 64) {
        float4 v4 = dr4[i4];
        const int mb = i4 * 4;
        float vv[4] = { v4.x, v4.y, v4.z, v4.w };
#pragma unroll
        for (int c = 0; c < 4; c++) {
            float v = vv[c];
            if (v < tv[KNB - 1]) {
                tv[KNB - 1] = v; ti[KNB - 1] = mb + c;
#pragma unroll
                for (int q = KNB - 1; q > 0; q--) {
                    if (tv[q] < tv[q - 1]) {
                        float fv = tv[q]; tv[q] = tv[q - 1]; tv[q - 1] = fv;
                        int   fi = ti[q]; ti[q] = ti[q - 1]; ti[q - 1] = fi;
                    }
                }
            }
        }
    }

    __shared__ float sv[256 * KNB];
    __shared__ int   si[256 * KNB];
#pragma unroll
    for (int q = 0; q < KNB; q++) {
        sv[threadIdx.x * KNB + q] = tv[q];
        si[threadIdx.x * KNB + q] = ti[q];
    }

    for (int stride = 32; stride >= 1; stride >>= 1) {
        __syncthreads();
        if (g < (unsigned)stride) {
            float* Av = &sv[(r * 64 + g) * KNB];
            int*   Ai = &si[(r * 64 + g) * KNB];
            float* Bv = &sv[(r * 64 + g + stride) * KNB];
            int*   Bi = &si[(r * 64 + g + stride) * KNB];
            float ov[KNB]; int oi[KNB];
            int ia = 0, ib = 0;
#pragma unroll
            for (int q = 0; q < KNB; q++) {
                float va = (ia < KNB) ? Av[ia] : INFINITY;
                float vb = (ib < KNB) ? Bv[ib] : INFINITY;
                int xa = (ia < KNB) ? Ai[ia] : 0x7fffffff;
                int xb = (ib < KNB) ? Bi[ib] : 0x7fffffff;
                bool takeA = (va < vb) || (va == vb && xa < xb);
                ov[q] = takeA ? va : vb;
                oi[q] = takeA ? xa : xb;
                if (takeA) ia++; else ib++;
            }
#pragma unroll
            for (int q = 0; q < KNB; q++) { Av[q] = ov[q]; Ai[q] = oi[q]; }
        }
    }
    __syncthreads();

    // ---- gather + max-edge: 64 threads per row, 3 channels each
    {
        const int* nn9 = &si[(r * 64) * KNB];
        const float* hb = d_h + (size_t)b * NN * CC;
        const float* hr = d_h + (size_t)row * CC;
        float* gb = d_gbuf + (size_t)row * CC2;
#pragma unroll
        for (int e = 0; e < 3; e++) {
            int c = g + e * 64;
            float hn = hr[c];
            float mx = -INFINITY;
#pragma unroll
            for (int j = 0; j < KNB; j++)
                mx = fmaxf(mx, hb[(size_t)nn9[j] * CC + c] - hn);
            gb[c]      = hn;
            gb[CC + c] = mx;
        }
    }
}

// ---------------- transpose (B,N,C)->(B,C,N) + residual ---------------------
__global__ void out_kernel(const float* __restrict__ x, float* __restrict__ out) {
    __shared__ float tile[32][33];
    const int b = blockIdx.z;
    const int n0 = blockIdx.x * 32, c0 = blockIdx.y * 32;
    const int tx = threadIdx.x, ty = threadIdx.y;
#pragma unroll
    for (int i = 0; i < 32; i += 8)
        tile[ty + i][tx] = d_obuf[((size_t)b * NN + n0 + ty + i) * CC + c0 + tx];
    __syncthreads();
#pragma unroll
    for (int i = 0; i < 32; i += 8) {
        int c = c0 + ty + i, n = n0 + tx;
        size_t o = ((size_t)b * CC + c) * NN + n;
        out[o] = tile[tx][ty + i] + x[o];
    }
}

// ---------------- launch ----------------------------------------------------
extern "C" void kernel_launch(void* const* d_in, const int* in_sizes, int n_in,
                              void* d_out, int out_size)
{
    (void)in_sizes; (void)n_in; (void)out_size;
    const float* x     = (const float*)d_in[0];
    const float* fc1_w = (const float*)d_in[1];
    const float* fc1_b = (const float*)d_in[2];
    const float* bn1_g = (const float*)d_in[3];
    const float* bn1_b = (const float*)d_in[4];
    const float* bn1_m = (const float*)d_in[5];
    const float* bn1_v = (const float*)d_in[6];
    const float* gc_w  = (const float*)d_in[7];
    const float* gc_b  = (const float*)d_in[8];
    const float* bng_g = (const float*)d_in[9];
    const float* bng_b = (const float*)d_in[10];
    const float* bng_m = (const float*)d_in[11];
    const float* bng_v = (const float*)d_in[12];
    const float* fc2_w = (const float*)d_in[13];
    const float* fc2_b = (const float*)d_in[14];
    const float* bn2_g = (const float*)d_in[15];
    const float* bn2_b = (const float*)d_in[16];
    const float* bn2_m = (const float*)d_in[17];
    const float* bn2_v = (const float*)d_in[18];
    float* out = (float*)d_out;

    cudaFuncSetAttribute(dist_mma_kernel,
                         cudaFuncAttributeMaxDynamicSharedMemorySize, DSM_TOTAL);

    // 1: rel position table (56x56)
    rel_table_kernel<<<25, 128>>>();
    // 2: fc1 + bn1 -> h
    gemm_kernel<0><<<dim3(2, 25, BB), 256>>>(x, fc1_w, fc1_b, bn1_g, bn1_b, bn1_m, bn1_v);
    // 3: normalize rows -> sq + bf16 concat split buffers
    norm_kernel<<<BB * NN, 64>>>();
    // 4: dist via mma.sync bf16 split (3-stage pipeline)  [ncu capture slot]
    dist_mma_kernel<<<dim3(25, 25, BB), 256, DSM_TOTAL>>>();
    // 5: fused top-9 + gather/max-edge, 4 rows/block -> g = [h, d]
    topk_gather_kernel<<<BB * NN / 4, 256>>>();
    // 6: grouped conv + bn + gelu -> y
    gemm_kernel<3><<<dim3(1, 25, BB * 4), 256>>>(nullptr, gc_w, gc_b, bng_g, bng_b, bng_m, bng_v);
    // 7: fc2 + bn2 -> o
    gemm_kernel<4><<<dim3(2, 196, 1), 256>>>(nullptr, fc2_w, fc2_b, bn2_g, bn2_b, bn2_m, bn2_v);
    // 8: transpose + residual -> out
    out_kernel<<<dim3(98, 6, BB), dim3(32, 8)>>>(x, out);
}

// round 13
// speedup vs baseline: 1.3239x; 1.0994x over previous
#include <cuda_runtime.h>
#include <cuda_bf16.h>
#include <math.h>
#include <stdint.h>

// Problem constants (fixed shapes from setup_inputs)
#define BB  8
#define CC  192
#define HH  56
#define WW  56
#define NN  3136            // H*W
#define CC2 384             // 2*C
#define CG  96              // C2/4
#define KNB 9               // K_NEIGHBORS
#define BNEPS 1e-5f
#define KTOT 576            // 3*CC  (hi|hi|lo concat)
#define KSLAB 64
#define NSLABS 9            // KTOT/KSLAB

// ---------------- scratch (static device globals; no runtime alloc) --------
__device__ float d_R   [56 * 56];                          // rel position table
__device__ float d_h   [(size_t)BB * NN * CC];             // 19.3 MB
__device__ __nv_bfloat16 d_xa[(size_t)BB * NN * KTOT];     // 28.9 MB  [hi|hi|lo]
__device__ __nv_bfloat16 d_xb[(size_t)BB * NN * KTOT];     // 28.9 MB  [hi|lo|hi]
__device__ float d_sq  [BB * NN];
__device__ float d_dist[(size_t)BB * NN * NN];             // 314.7 MB
__device__ float d_gbuf[(size_t)BB * NN * CC2];            // 38.6 MB
__device__ float d_ybuf[(size_t)BB * NN * CC2];            // 38.6 MB
__device__ float d_obuf[(size_t)BB * NN * CC];             // 19.3 MB

__device__ __forceinline__ uint32_t smem_u32(const void* p) {
    uint32_t a;
    asm("{ .reg .u64 t; cvta.to.shared.u64 t, %1; cvt.u32.u64 %0, t; }"
        : "=r"(a) : "l"(p));
    return a;
}

// ---------------- rel position table: R[a][b] = -2/C * emb(a).emb(b) --------
__global__ void rel_table_kernel() {
    int p = blockIdx.x * 128 + threadIdx.x;
    if (p >= 56 * 56) return;
    int a = p / 56, b = p - (p / 56) * 56;
    float s = 0.0f;
#pragma unroll 1
    for (int i = 0; i < 48; i++) {
        float wv = expf(-logf(10000.0f) * (float)i / 48.0f);
        float sa, ca, sb, cb;
        sincosf((float)a * wv, &sa, &ca);
        sincosf((float)b * wv, &sb, &cb);
        s += sa * sb + ca * cb;
    }
    d_R[p] = (-2.0f / (float)CC) * s;
}

// ---------------- 128x128x16 double-buffered SGEMM (modes 0,3,4) -----------
template <int MODE>
__global__ void __launch_bounds__(256, 2)
gemm_kernel(const float* __restrict__ Ain, const float* __restrict__ Bin,
            const float* __restrict__ q0, const float* __restrict__ q1,
            const float* __restrict__ q2, const float* __restrict__ q3,
            const float* __restrict__ q4)
{
    constexpr bool AKM = (MODE == 0);     // A stored K-major

    int M, Nc, K, lda, ldb;
    const float* A;
    const float* B;
    const int bz = blockIdx.z;

    if (MODE == 0) {
        A = Ain + (size_t)bz * CC * NN;  B = Bin;
        M = NN; Nc = CC; K = CC; lda = NN; ldb = CC;
    } else if (MODE == 3) {
        int b = bz >> 2, g = bz & 3;
        A = d_gbuf + (size_t)b * NN * CC2 + g * CG;
        B = Bin + (size_t)g * CG * CG;
        M = NN; Nc = CG; K = CG; lda = CC2; ldb = CG;
    } else {
        A = d_ybuf; B = Bin;
        M = BB * NN; Nc = CC; K = CC2; lda = CC2; ldb = CC2;
    }

    __shared__ float As[2][16][128];
    __shared__ float Bs[2][16][128];

    const int tid = threadIdx.x;
    const int tx = tid & 15;
    const int ty = tid >> 4;
    const int m0 = blockIdx.y * 128;
    const int n0 = blockIdx.x * 128;

    const float* aptr0;
    const float* aptr1;
    int a_km_k = 0, a_km_m = 0;
    int a_rm_r = 0, a_rm_kq = 0;
    if (AKM) {
        a_km_k = tid >> 5;
        a_km_m = (tid & 31) * 4;
        int mc = min(m0 + a_km_m, M - 4);
        aptr0 = A + (size_t)a_km_k * lda + mc;
        aptr1 = A + (size_t)(a_km_k + 8) * lda + mc;
    } else {
        a_rm_r  = tid >> 1;
        a_rm_kq = (tid & 1) * 8;
        int rc = min(m0 + a_rm_r, M - 1);
        aptr0 = A + (size_t)rc * lda + a_rm_kq;
        aptr1 = aptr0 + 4;
    }
    const int b_rm_r  = tid >> 1;
    const int b_rm_kq = (tid & 1) * 8;
    const float* bptr0 = B + (size_t)min(n0 + b_rm_r, Nc - 1) * ldb + b_rm_kq;
    const float* bptr1 = bptr0 + 4;

    float4 ra0, ra1, rb0, rb1;
    ra0 = *reinterpret_cast<const float4*>(aptr0);
    ra1 = *reinterpret_cast<const float4*>(aptr1);
    rb0 = *reinterpret_cast<const float4*>(bptr0);
    rb1 = *reinterpret_cast<const float4*>(bptr1);
    if (AKM) {
        *reinterpret_cast<float4*>(&As[0][a_km_k][a_km_m])     = ra0;
        *reinterpret_cast<float4*>(&As[0][a_km_k + 8][a_km_m]) = ra1;
    } else {
        As[0][a_rm_kq + 0][a_rm_r] = ra0.x; As[0][a_rm_kq + 1][a_rm_r] = ra0.y;
        As[0][a_rm_kq + 2][a_rm_r] = ra0.z; As[0][a_rm_kq + 3][a_rm_r] = ra0.w;
        As[0][a_rm_kq + 4][a_rm_r] = ra1.x; As[0][a_rm_kq + 5][a_rm_r] = ra1.y;
        As[0][a_rm_kq + 6][a_rm_r] = ra1.z; As[0][a_rm_kq + 7][a_rm_r] = ra1.w;
    }
    Bs[0][b_rm_kq + 0][b_rm_r] = rb0.x; Bs[0][b_rm_kq + 1][b_rm_r] = rb0.y;
    Bs[0][b_rm_kq + 2][b_rm_r] = rb0.z; Bs[0][b_rm_kq + 3][b_rm_r] = rb0.w;
    Bs[0][b_rm_kq + 4][b_rm_r] = rb1.x; Bs[0][b_rm_kq + 5][b_rm_r] = rb1.y;
    Bs[0][b_rm_kq + 6][b_rm_r] = rb1.z; Bs[0][b_rm_kq + 7][b_rm_r] = rb1.w;
    __syncthreads();

    float acc[8][8];
#pragma unroll
    for (int i = 0; i < 8; i++)
#pragma unroll
        for (int j = 0; j < 8; j++) acc[i][j] = 0.0f;

    const int T = K >> 4;
    for (int t = 0; t < T; t++) {
        const int cur = t & 1;
        if (t + 1 < T) {
            if (AKM) { aptr0 += (size_t)16 * lda; aptr1 += (size_t)16 * lda; }
            else     { aptr0 += 16;               aptr1 += 16; }
            bptr0 += 16; bptr1 += 16;
            ra0 = *reinterpret_cast<const float4*>(aptr0);
            ra1 = *reinterpret_cast<const float4*>(aptr1);
            rb0 = *reinterpret_cast<const float4*>(bptr0);
            rb1 = *reinterpret_cast<const float4*>(bptr1);
        }
#pragma unroll
        for (int kk = 0; kk < 16; kk++) {
            float af[8], bf[8];
            *reinterpret_cast<float4*>(&af[0]) = *reinterpret_cast<const float4*>(&As[cur][kk][ty * 4]);
            *reinterpret_cast<float4*>(&af[4]) = *reinterpret_cast<const float4*>(&As[cur][kk][64 + ty * 4]);
            *reinterpret_cast<float4*>(&bf[0]) = *reinterpret_cast<const float4*>(&Bs[cur][kk][tx * 4]);
            *reinterpret_cast<float4*>(&bf[4]) = *reinterpret_cast<const float4*>(&Bs[cur][kk][64 + tx * 4]);
#pragma unroll
            for (int i = 0; i < 8; i++)
#pragma unroll
                for (int j = 0; j < 8; j++) acc[i][j] += af[i] * bf[j];
        }
        if (t + 1 < T) {
            const int nxt = cur ^ 1;
            if (AKM) {
                *reinterpret_cast<float4*>(&As[nxt][a_km_k][a_km_m])     = ra0;
                *reinterpret_cast<float4*>(&As[nxt][a_km_k + 8][a_km_m]) = ra1;
            } else {
                As[nxt][a_rm_kq + 0][a_rm_r] = ra0.x; As[nxt][a_rm_kq + 1][a_rm_r] = ra0.y;
                As[nxt][a_rm_kq + 2][a_rm_r] = ra0.z; As[nxt][a_rm_kq + 3][a_rm_r] = ra0.w;
                As[nxt][a_rm_kq + 4][a_rm_r] = ra1.x; As[nxt][a_rm_kq + 5][a_rm_r] = ra1.y;
                As[nxt][a_rm_kq + 6][a_rm_r] = ra1.z; As[nxt][a_rm_kq + 7][a_rm_r] = ra1.w;
            }
            Bs[nxt][b_rm_kq + 0][b_rm_r] = rb0.x; Bs[nxt][b_rm_kq + 1][b_rm_r] = rb0.y;
            Bs[nxt][b_rm_kq + 2][b_rm_r] = rb0.z; Bs[nxt][b_rm_kq + 3][b_rm_r] = rb0.w;
            Bs[nxt][b_rm_kq + 4][b_rm_r] = rb1.x; Bs[nxt][b_rm_kq + 5][b_rm_r] = rb1.y;
            Bs[nxt][b_rm_kq + 6][b_rm_r] = rb1.z; Bs[nxt][b_rm_kq + 7][b_rm_r] = rb1.w;
        }
        __syncthreads();
    }

    int rows[8], cols[8];
#pragma unroll
    for (int i = 0; i < 4; i++) {
        rows[i]     = m0 + ty * 4 + i;
        rows[i + 4] = m0 + 64 + ty * 4 + i;
        cols[i]     = n0 + tx * 4 + i;
        cols[i + 4] = n0 + 64 + tx * 4 + i;
    }

    if (MODE == 0) {
        float sc[8], bi[8];
#pragma unroll
        for (int j = 0; j < 8; j++) {
            if (cols[j] < Nc) {
                float s = q1[cols[j]] * rsqrtf(q4[cols[j]] + BNEPS);
                sc[j] = s;
                bi[j] = (q0[cols[j]] - q3[cols[j]]) * s + q2[cols[j]];
            } else { sc[j] = 0.f; bi[j] = 0.f; }
        }
        float* hb = d_h + (size_t)bz * NN * CC;
#pragma unroll
        for (int i = 0; i < 8; i++) {
            if (rows[i] >= M) continue;
#pragma unroll
            for (int j = 0; j < 8; j++)
                if (cols[j] < Nc)
                    hb[(size_t)rows[i] * CC + cols[j]] = acc[i][j] * sc[j] + bi[j];
        }
    } else if (MODE == 3) {
        int b = bz >> 2, g = bz & 3;
        float sc[8], bi[8];
        int ch[8];
#pragma unroll
        for (int j = 0; j < 8; j++) {
            ch[j] = g * CG + cols[j];
            if (cols[j] < Nc) {
                float s = q1[ch[j]] * rsqrtf(q4[ch[j]] + BNEPS);
                sc[j] = s;
                bi[j] = (q0[ch[j]] - q3[ch[j]]) * s + q2[ch[j]];
            } else { sc[j] = 0.f; bi[j] = 0.f; }
        }
        float* yb = d_ybuf + (size_t)b * NN * CC2;
#pragma unroll
        for (int i = 0; i < 8; i++) {
            if (rows[i] >= M) continue;
#pragma unroll
            for (int j = 0; j < 8; j++)
                if (cols[j] < Nc) {
                    float t2 = acc[i][j] * sc[j] + bi[j];
                    yb[(size_t)rows[i] * CC2 + ch[j]] = t2 * normcdff(t2);
                }
        }
    } else { // MODE 4
        float sc[8], bi[8];
#pragma unroll
        for (int j = 0; j < 8; j++) {
            if (cols[j] < Nc) {
                float s = q1[cols[j]] * rsqrtf(q4[cols[j]] + BNEPS);
                sc[j] = s;
                bi[j] = (q0[cols[j]] - q3[cols[j]]) * s + q2[cols[j]];
            } else { sc[j] = 0.f; bi[j] = 0.f; }
        }
#pragma unroll
        for (int i = 0; i < 8; i++) {
            if (rows[i] >= M) continue;
#pragma unroll
            for (int j = 0; j < 8; j++)
                if (cols[j] < Nc)
                    d_obuf[(size_t)rows[i] * CC + cols[j]] = acc[i][j] * sc[j] + bi[j];
        }
    }
}

// ---------------- L2 normalize + sq + bf16 hi/lo concat buffers --------------
__global__ void norm_kernel() {
    int row = blockIdx.x;
    const float* hr = d_h + (size_t)row * CC;
    int t = threadIdx.x;                    // 64 threads
    float a0 = hr[t], a1 = hr[t + 64], a2 = hr[t + 128];
    float ss = a0 * a0 + a1 * a1 + a2 * a2;
#pragma unroll
    for (int o = 16; o > 0; o >>= 1) ss += __shfl_down_sync(0xffffffffu, ss, o);
    __shared__ float w1[2], w2[2];
    if ((t & 31) == 0) w1[t >> 5] = ss;
    __syncthreads();
    float norm = sqrtf(w1[0] + w1[1]);
    float inv = 1.0f / fmaxf(norm, 1e-12f);
    float xv[3] = { a0 * inv, a1 * inv, a2 * inv };
    float s2 = xv[0] * xv[0] + xv[1] * xv[1] + xv[2] * xv[2];
#pragma unroll
    for (int o = 16; o > 0; o >>= 1) s2 += __shfl_down_sync(0xffffffffu, s2, o);
    if ((t & 31) == 0) w2[t >> 5] = s2;

    __nv_bfloat16* xa = d_xa + (size_t)row * KTOT;
    __nv_bfloat16* xb = d_xb + (size_t)row * KTOT;
#pragma unroll
    for (int e = 0; e < 3; e++) {
        int c = t + e * 64;
        float x = xv[e];
        __nv_bfloat16 h = __float2bfloat16(x);
        __nv_bfloat16 l = __float2bfloat16(x - __bfloat162float(h));
        xa[c]       = h;  xa[192 + c] = h;  xa[384 + c] = l;
        xb[c]       = h;  xb[192 + c] = l;  xb[384 + c] = h;
    }
    __syncthreads();
    if (t == 0) d_sq[row] = w2[0] + w2[1];
}

// ---------------- dist via mma.sync bf16 (K=576 concat split) ----------------
// CTA 128x128, 8 warps 4(m)x2(n), warp tile 32x64, K-slab 64, cp.async dbl-buf.
// rel via 56x56 smem table; C staging stride 133 (odd) => conflict-free epilogue.
#define SROW 144                       // smem tile row bytes (72 bf16: 64 + 8 pad)
#define TILE_B (128 * SROW)            // 18432
#define SM_R   0                       // 12544 B
#define SM_IDX 12544                   // 2048 B (yyR,xxR,yyC,xxC int[128])
#define SM_BUF 14592
#define DS_STRIDE 133
#define DSM_TOTAL (SM_BUF + 4 * TILE_B)   // 88320 (>= SM_BUF + 128*133*4)
__global__ void __launch_bounds__(256)
dist_mma_kernel() {
    if (blockIdx.y > blockIdx.x) return;
    extern __shared__ char smem[];
    const int tid = threadIdx.x, w = tid >> 5, lane = tid & 31;
    const int b = blockIdx.z;
    const int m0 = blockIdx.y * 128, n0 = blockIdx.x * 128;

    float* Rs  = reinterpret_cast<float*>(smem + SM_R);
    int*   yyR = reinterpret_cast<int*>(smem + SM_IDX);
    int*   xxR = yyR + 128;
    int*   yyC = yyR + 256;
    int*   xxC = yyR + 384;

    for (int i = tid; i < 56 * 56; i += 256) Rs[i] = d_R[i];
    if (tid < 128) {
        int rg = min(m0 + tid, NN - 1);
        yyR[tid] = rg / 56; xxR[tid] = rg - (rg / 56) * 56;
        int cg = min(n0 + tid, NN - 1);
        yyC[tid] = cg / 56; xxC[tid] = cg - (cg / 56) * 56;
    }

    const uint32_t sbuf = smem_u32(smem + SM_BUF);
    const uint32_t sAq[2] = { sbuf, sbuf + TILE_B };
    const uint32_t sBq[2] = { sbuf + 2 * TILE_B, sbuf + 3 * TILE_B };

    const __nv_bfloat16* baseA = d_xa + (size_t)b * NN * KTOT;
    const __nv_bfloat16* baseB = d_xb + (size_t)b * NN * KTOT;

    auto issue = [&](int s) {
        const int k0b = s * KSLAB * 2;
        const uint32_t dA = sAq[s & 1], dB = sBq[s & 1];
#pragma unroll
        for (int c = 0; c < 4; c++) {
            int ch = tid + c * 256;
            int row = ch >> 3, cg = (ch & 7) * 16;
            const char* ga = (const char*)(baseA + (size_t)min(m0 + row, NN - 1) * KTOT) + k0b + cg;
            const char* gb = (const char*)(baseB + (size_t)min(n0 + row, NN - 1) * KTOT) + k0b + cg;
            uint32_t off = row * SROW + cg;
            asm volatile("cp.async.cg.shared.global [%0], [%1], 16;" :: "r"(dA + off), "l"(ga));
            asm volatile("cp.async.cg.shared.global [%0], [%1], 16;" :: "r"(dB + off), "l"(gb));
        }
        asm volatile("cp.async.commit_group;" ::: "memory");
    };

    issue(0);
    issue(1);

    float acc[2][8][4];
#pragma unroll
    for (int i = 0; i < 2; i++)
#pragma unroll
        for (int j = 0; j < 8; j++)
#pragma unroll
            for (int k = 0; k < 4; k++) acc[i][j][k] = 0.0f;

    const int wm = w & 3;                         // rows wm*32
    const int wn = w >> 2;                        // cols wn*64
    const int aRow  = lane & 15;
    const int aColB = ((lane >> 4) * 8) * 2;
    const int bNr   = ((lane >> 4) << 3) + (lane & 7);
    const int bColB = (((lane >> 3) & 1) * 8) * 2;

    for (int s = 0; s < NSLABS; s++) {
        if (s < NSLABS - 1)
            asm volatile("cp.async.wait_group 1;" ::: "memory");
        else
            asm volatile("cp.async.wait_group 0;" ::: "memory");
        __syncthreads();
        const uint32_t cA = sAq[s & 1], cB = sBq[s & 1];
#pragma unroll
        for (int kk = 0; kk < 4; kk++) {
            const int k0b = kk * 32;
            uint32_t af[2][4];
#pragma unroll
            for (int mi = 0; mi < 2; mi++) {
                uint32_t addr = cA + (wm * 32 + mi * 16 + aRow) * SROW + k0b + aColB;
                asm volatile(
                    "ldmatrix.sync.aligned.m8n8.x4.shared.b16 {%0,%1,%2,%3}, [%4];"
                    : "=r"(af[mi][0]), "=r"(af[mi][1]), "=r"(af[mi][2]), "=r"(af[mi][3])
                    : "r"(addr));
            }
            uint32_t bfv[4][4];
#pragma unroll
            for (int nb = 0; nb < 4; nb++) {
                uint32_t addr = cB + (wn * 64 + nb * 16 + bNr) * SROW + k0b + bColB;
                asm volatile(
                    "ldmatrix.sync.aligned.m8n8.x4.shared.b16 {%0,%1,%2,%3}, [%4];"
                    : "=r"(bfv[nb][0]), "=r"(bfv[nb][1]), "=r"(bfv[nb][2]), "=r"(bfv[nb][3])
                    : "r"(addr));
            }
#pragma unroll
            for (int mi = 0; mi < 2; mi++)
#pragma unroll
                for (int ni = 0; ni < 8; ni++) {
                    uint32_t b0 = bfv[ni >> 1][(ni & 1) * 2 + 0];
                    uint32_t b1 = bfv[ni >> 1][(ni & 1) * 2 + 1];
                    asm volatile(
                        "mma.sync.aligned.m16n8k16.row.col.f32.bf16.bf16.f32 "
                        "{%0,%1,%2,%3}, {%4,%5,%6,%7}, {%8,%9}, {%0,%1,%2,%3};"
                        : "+f"(acc[mi][ni][0]), "+f"(acc[mi][ni][1]),
                          "+f"(acc[mi][ni][2]), "+f"(acc[mi][ni][3])
                        : "r"(af[mi][0]), "r"(af[mi][1]), "r"(af[mi][2]), "r"(af[mi][3]),
                          "r"(b0), "r"(b1));
                }
        }
        __syncthreads();
        if (s + 2 < NSLABS) issue(s + 2);
    }

    // ---- stage C to smem [128][DS_STRIDE=133] (odd stride: conflict-free reads)
    float* Ds = reinterpret_cast<float*>(smem + SM_BUF);
#pragma unroll
    for (int mi = 0; mi < 2; mi++) {
        int r0 = wm * 32 + mi * 16 + (lane >> 2);
        int c0 = wn * 64 + (lane & 3) * 2;
#pragma unroll
        for (int ni = 0; ni < 8; ni++) {
            int cc = c0 + ni * 8;
            Ds[r0 * DS_STRIDE + cc]           = acc[mi][ni][0];
            Ds[r0 * DS_STRIDE + cc + 1]       = acc[mi][ni][1];
            Ds[(r0 + 8) * DS_STRIDE + cc]     = acc[mi][ni][2];
            Ds[(r0 + 8) * DS_STRIDE + cc + 1] = acc[mi][ni][3];
        }
    }
    __syncthreads();

    float* db = d_dist + (size_t)b * NN * NN;
    const float* sqb = d_sq + b * NN;

    // phase 1: mirror tile; lane = row (coalesced stores, conflict-free LDS)
    if (blockIdx.x != blockIdx.y) {
        for (int cl = w; cl < 128; cl += 8) {
            int m = n0 + cl;
            if (m >= NN) continue;
            float* dbm = db + (size_t)m * NN;
            const int yc = yyC[cl], xc = xxC[cl];
#pragma unroll
            for (int rq = 0; rq < 4; rq++) {
                int rl = rq * 32 + lane;
                int rg = m0 + rl;
                if (rg >= NN) continue;
                float v = Ds[rl * DS_STRIDE + cl];
                float relv = Rs[yyR[rl] * 56 + yc] + Rs[xxR[rl] * 56 + xc];
                dbm[rg] = sqb[rg] - 2.0f * v + relv;
            }
        }
    }

    // phase 2: normal tile; thread = column, sweep rows (conflict-free LDS,
    // coalesced scalar stores, broadcast row-index reads)
    {
        const int c = tid & 127;
        const int rh = (tid >> 7) * 64;
        const int gc = n0 + c;
        if (gc < NN) {
            const float sqc = sqb[gc];
            const int yc = yyC[c], xc = xxC[c];
#pragma unroll 1
            for (int r = 0; r < 64; r++) {
                int rl = rh + r;
                int rg = m0 + rl;
                if (rg >= NN) break;
                float v = Ds[rl * DS_STRIDE + c];
                float relv = Rs[yyR[rl] * 56 + yc] + Rs[xxR[rl] * 56 + xc];
                db[(size_t)rg * NN + gc] = sqc - 2.0f * v + relv;
            }
        }
    }
}

// ---------------- fused top-9 + gather/max-edge (4 rows per block) -----------
__global__ void __launch_bounds__(256) topk_gather_kernel() {
    const int r = threadIdx.x >> 6;          // 0..3 row within block
    const int g = threadIdx.x & 63;          // 0..63 lane within row group
    const int row = blockIdx.x * 4 + r;      // global row (b*N + n)
    const int b = row / NN, n = row % NN;
    const float4* dr4 = reinterpret_cast<const float4*>(
        d_dist + (size_t)b * NN * NN + (size_t)n * NN);

    float tv[KNB];
    int   ti[KNB];
#pragma unroll
    for (int q = 0; q < KNB; q++) { tv[q] = INFINITY; ti[q] = 0x7fffffff; }

    for (int i4 = g; i4 < NN / 4; i4 += 64) {
        float4 v4 = dr4[i4];
        const int mb = i4 * 4;
        float vv[4] = { v4.x, v4.y, v4.z, v4.w };
#pragma unroll
        for (int c = 0; c < 4; c++) {
            float v = vv[c];
            if (v < tv[KNB - 1]) {
                tv[KNB - 1] = v; ti[KNB - 1] = mb + c;
#pragma unroll
                for (int q = KNB - 1; q > 0; q--) {
                    if (tv[q] < tv[q - 1]) {
                        float fv = tv[q]; tv[q] = tv[q - 1]; tv[q - 1] = fv;
                        int   fi = ti[q]; ti[q] = ti[q - 1]; ti[q - 1] = fi;
                    }
                }
            }
        }
    }

    __shared__ float sv[256 * KNB];
    __shared__ int   si[256 * KNB];
#pragma unroll
    for (int q = 0; q < KNB; q++) {
        sv[threadIdx.x * KNB + q] = tv[q];
        si[threadIdx.x * KNB + q] = ti[q];
    }

    for (int stride = 32; stride >= 1; stride >>= 1) {
        __syncthreads();
        if (g < (unsigned)stride) {
            float* Av = &sv[(r * 64 + g) * KNB];
            int*   Ai = &si[(r * 64 + g) * KNB];
            float* Bv = &sv[(r * 64 + g + stride) * KNB];
            int*   Bi = &si[(r * 64 + g + stride) * KNB];
            float ov[KNB]; int oi[KNB];
            int ia = 0, ib = 0;
#pragma unroll
            for (int q = 0; q < KNB; q++) {
                float va = (ia < KNB) ? Av[ia] : INFINITY;
                float vb = (ib < KNB) ? Bv[ib] : INFINITY;
                int xa = (ia < KNB) ? Ai[ia] : 0x7fffffff;
                int xb = (ib < KNB) ? Bi[ib] : 0x7fffffff;
                bool takeA = (va < vb) || (va == vb && xa < xb);
                ov[q] = takeA ? va : vb;
                oi[q] = takeA ? xa : xb;
                if (takeA) ia++; else ib++;
            }
#pragma unroll
            for (int q = 0; q < KNB; q++) { Av[q] = ov[q]; Ai[q] = oi[q]; }
        }
    }
    __syncthreads();

    // ---- gather + max-edge: 64 threads per row, 3 channels each
    {
        const int* nn9 = &si[(r * 64) * KNB];
        const float* hb = d_h + (size_t)b * NN * CC;
        const float* hr = d_h + (size_t)row * CC;
        float* gb = d_gbuf + (size_t)row * CC2;
#pragma unroll
        for (int e = 0; e < 3; e++) {
            int c = g + e * 64;
            float hn = hr[c];
            float mx = -INFINITY;
#pragma unroll
            for (int j = 0; j < KNB; j++)
                mx = fmaxf(mx, hb[(size_t)nn9[j] * CC + c] - hn);
            gb[c]      = hn;
            gb[CC + c] = mx;
        }
    }
}

// ---------------- transpose (B,N,C)->(B,C,N) + residual ---------------------
__global__ void out_kernel(const float* __restrict__ x, float* __restrict__ out) {
    __shared__ float tile[32][33];
    const int b = blockIdx.z;
    const int n0 = blockIdx.x * 32, c0 = blockIdx.y * 32;
    const int tx = threadIdx.x, ty = threadIdx.y;
#pragma unroll
    for (int i = 0; i < 32; i += 8)
        tile[ty + i][tx] = d_obuf[((size_t)b * NN + n0 + ty + i) * CC + c0 + tx];
    __syncthreads();
#pragma unroll
    for (int i = 0; i < 32; i += 8) {
        int c = c0 + ty + i, n = n0 + tx;
        size_t o = ((size_t)b * CC + c) * NN + n;
        out[o] = tile[tx][ty + i] + x[o];
    }
}

// ---------------- launch ----------------------------------------------------
extern "C" void kernel_launch(void* const* d_in, const int* in_sizes, int n_in,
                              void* d_out, int out_size)
{
    (void)in_sizes; (void)n_in; (void)out_size;
    const float* x     = (const float*)d_in[0];
    const float* fc1_w = (const float*)d_in[1];
    const float* fc1_b = (const float*)d_in[2];
    const float* bn1_g = (const float*)d_in[3];
    const float* bn1_b = (const float*)d_in[4];
    const float* bn1_m = (const float*)d_in[5];
    const float* bn1_v = (const float*)d_in[6];
    const float* gc_w  = (const float*)d_in[7];
    const float* gc_b  = (const float*)d_in[8];
    const float* bng_g = (const float*)d_in[9];
    const float* bng_b = (const float*)d_in[10];
    const float* bng_m = (const float*)d_in[11];
    const float* bng_v = (const float*)d_in[12];
    const float* fc2_w = (const float*)d_in[13];
    const float* fc2_b = (const float*)d_in[14];
    const float* bn2_g = (const float*)d_in[15];
    const float* bn2_b = (const float*)d_in[16];
    const float* bn2_m = (const float*)d_in[17];
    const float* bn2_v = (const float*)d_in[18];
    float* out = (float*)d_out;

    cudaFuncSetAttribute(dist_mma_kernel,
                         cudaFuncAttributeMaxDynamicSharedMemorySize, DSM_TOTAL);

    // 1: rel position table (56x56)
    rel_table_kernel<<<25, 128>>>();
    // 2: fc1 + bn1 -> h
    gemm_kernel<0><<<dim3(2, 25, BB), 256>>>(x, fc1_w, fc1_b, bn1_g, bn1_b, bn1_m, bn1_v);
    // 3: normalize rows -> sq + bf16 concat split buffers
    norm_kernel<<<BB * NN, 64>>>();
    // 4: dist via mma.sync bf16 split (round-11 double-buffer)  [ncu slot]
    dist_mma_kernel<<<dim3(25, 25, BB), 256, DSM_TOTAL>>>();
    // 5: fused top-9 + gather/max-edge, 4 rows/block -> g = [h, d]
    topk_gather_kernel<<<BB * NN / 4, 256>>>();
    // 6: grouped conv + bn + gelu -> y
    gemm_kernel<3><<<dim3(1, 25, BB * 4), 256>>>(nullptr, gc_w, gc_b, bng_g, bng_b, bng_m, bng_v);
    // 7: fc2 + bn2 -> o
    gemm_kernel<4><<<dim3(2, 196, 1), 256>>>(nullptr, fc2_w, fc2_b, bn2_g, bn2_b, bn2_m, bn2_v);
    // 8: transpose + residual -> out
    out_kernel<<<dim3(98, 6, BB), dim3(32, 8)>>>(x, out);
}